// round 6
// baseline (speedup 1.0000x reference)
#include <cuda_runtime.h>
#include <cuda_fp16.h>
#include <cstdint>
#include <cstddef>

#define BB   4
#define LL   1024
#define HH   16
#define DD   64
#define EMBN 1024
#define MAXREL 512
#define NREL (2*MAXREL + 1)

#define SH   72    // half stride, 64-wide tiles  (144B = 36 words == 4 mod 32)
#define SH2  136   // half stride, 128-wide tiles (272B = 68 words == 4 mod 32)
#define SQ   68    // float stride for SQK

// Scratch (allocation-free rule: device globals)
__device__ __half g_qh [BB*LL*HH*DD];
__device__ __half g_kh [BB*LL*HH*DD];
__device__ __half g_vh [BB*LL*HH*DD];
__device__ __half g_ctx[BB*LL*HH*DD];
__device__ __half g_relk_h[NREL*DD];
__device__ __half g_relv_h[NREL*DD];
__device__ __half g_Wfc_h[EMBN*EMBN];
__device__ unsigned char g_mask8[BB*LL*LL];

// ---------------------------------------------------------------------------
#define MMA_F16(d0,d1,d2,d3,a0,a1,a2,a3,b0,b1)                               \
    asm volatile("mma.sync.aligned.m16n8k16.row.col.f32.f16.f16.f32 "        \
                 "{%0,%1,%2,%3}, {%4,%5,%6,%7}, {%8,%9}, {%0,%1,%2,%3};"     \
                 : "+f"(d0), "+f"(d1), "+f"(d2), "+f"(d3)                    \
                 : "r"(a0), "r"(a1), "r"(a2), "r"(a3), "r"(b0), "r"(b1))

__device__ __forceinline__ uint32_t ldh2(const __half* p) {
    return *(const uint32_t*)p;
}
__device__ __forceinline__ int clampdiff(int d) {
    return d < -MAXREL ? -MAXREL : (d > MAXREL ? MAXREL : d);
}

// ---------------------------------------------------------------------------
// Pre: projections (y = 0..2) + fp16 constant conversion / mask pack (y = 3)
// ---------------------------------------------------------------------------
#define SA 68
__global__ __launch_bounds__(256) void pre_kernel(
    const float* __restrict__ query, const float* __restrict__ key_, const float* __restrict__ value,
    const float* __restrict__ Wq, const float* __restrict__ bq,
    const float* __restrict__ Wk, const float* __restrict__ bk,
    const float* __restrict__ Wv, const float* __restrict__ bv,
    const float* __restrict__ relk, const float* __restrict__ relv,
    const float* __restrict__ Wfc,  const int* __restrict__ mask)
{
    const int tid = threadIdx.x;

    if (blockIdx.y == 3) {
        // prep slice: grid-strided conversions
        const int stride = 1024 * 256;
        const int base = blockIdx.x * 256 + tid;
        for (int i = base; i < NREL*DD; i += stride) {
            g_relk_h[i] = __float2half_rn(relk[i]);
            g_relv_h[i] = __float2half_rn(relv[i]);
        }
        for (int i = base; i < EMBN*EMBN; i += stride)
            g_Wfc_h[i] = __float2half_rn(Wfc[i]);
        for (int i = base; i < BB*LL*LL; i += stride)
            g_mask8[i] = (unsigned char)(mask[i] != 0);
        return;
    }

    __shared__ float Xs[64*SA];
    __shared__ float Ws[64*SA];
    __shared__ float bs[64];

    const float* X; const float* W; const float* bias; __half* out;
    if (blockIdx.y == 0)      { X = query; W = Wq; bias = bq; out = g_qh; }
    else if (blockIdx.y == 1) { X = key_;  W = Wk; bias = bk; out = g_kh; }
    else                      { X = value; W = Wv; bias = bv; out = g_vh; }

    const size_t r0 = (size_t)blockIdx.x * 64;

    #pragma unroll
    for (int t = 0; t < 4; t++) {
        int idx = tid + t*256;
        int rr = idx >> 4, cc = (idx & 15) << 2;
        *(float4*)&Xs[rr*SA + cc] = *(const float4*)(X + (r0 + rr)*64 + cc);
        *(float4*)&Ws[rr*SA + cc] = *(const float4*)(W + (size_t)rr*64 + cc);
    }
    if (tid < 64) bs[tid] = bias[tid];
    __syncthreads();

    const int ty = tid >> 4, tx = tid & 15;
    float acc[4][4] = {};
    for (int e = 0; e < 64; e += 4) {
        float4 a[4], bb[4];
        #pragma unroll
        for (int ii = 0; ii < 4; ii++) a[ii]  = *(const float4*)&Xs[(ty + 16*ii)*SA + e];
        #pragma unroll
        for (int jj = 0; jj < 4; jj++) bb[jj] = *(const float4*)&Ws[(tx + 16*jj)*SA + e];
        #pragma unroll
        for (int ii = 0; ii < 4; ii++)
            #pragma unroll
            for (int jj = 0; jj < 4; jj++)
                acc[ii][jj] += a[ii].x*bb[jj].x + a[ii].y*bb[jj].y
                             + a[ii].z*bb[jj].z + a[ii].w*bb[jj].w;
    }
    #pragma unroll
    for (int ii = 0; ii < 4; ii++) {
        int i = ty + 16*ii;
        #pragma unroll
        for (int jj = 0; jj < 4; jj++) {
            int d = tx + 16*jj;
            out[(r0 + i)*64 + d] = __float2half_rn(acc[ii][jj] + bs[d]);
        }
    }
}

// ---------------------------------------------------------------------------
// Flash attention + relative bias, fp16 mma, 512 threads, 2 CTAs/SM.
// smem ~105 KB: SQK fp32, SrelH fp16 ring, Tkw single-block, Ph aliases Qh.
// ---------------------------------------------------------------------------
#define ATT_F_WORDS (64*SQ + 192)
#define ATT_H_WORDS (64*SH2 /*SrelH*/ + 3*64*SH /*Kh,Vt,PhQh*/ + 64*SH /*Tkw*/ + 2*64*SH2 /*Tvwt,Bnd*/)
#define ATT_SMEM_BYTES (ATT_F_WORDS*4 + ATT_H_WORDS*2)

__global__ __launch_bounds__(512, 2) void attn_kernel()
{
    extern __shared__ float smf[];
    float*  SQK   = smf;                      // 64 x SQ  (fp32 QK scores)
    float*  mrowS = SQK   + 64*SQ;            // 64
    float*  lrowS = mrowS + 64;               // 64
    float*  cscS  = lrowS + 64;               // 64
    __half* SrelH = (__half*)(cscS + 64);     // 64 x SH2 (fp16 rel-score ring)
    __half* Kh    = SrelH + 64*SH2;           // 64 x SH
    __half* Vt    = Kh    + 64*SH;            // 64 x SH   [d][kpos]
    __half* PhQh  = Vt    + 64*SH;            // 64 x SH   (Q at start, then probs)
    __half* Tkw   = PhQh  + 64*SH;            // 64 x SH   (new rel_k block only)
    __half* Tvwt  = Tkw   + 64*SH;            // 64 x SH2  rel_v ring [d][phys]
    __half* Bnd   = Tvwt  + 64*SH2;           // 64 x SH2  band probs

    const int b  = blockIdx.z;
    const int h  = blockIdx.y;
    const int q0 = blockIdx.x * 64;
    const int tid  = threadIdx.x;
    const int warp = tid >> 5, lane = tid & 31;
    const int g = lane >> 2, t = lane & 3;
    const int wr = warp >> 2, wc = warp & 3;     // 4x4 warp grid
    const int r0 = wr*16 + g;

    const int srow = tid >> 3;                   // softmax: 8 threads/row
    const int scol = (tid & 7) << 3;

    const int rr = tid >> 3, cc = (tid & 7) << 3; // staging: uint4/thread, 64x64
    const int kp = tid & 63, dg = tid >> 6;       // transpose: 8 d's per thread

    if (tid < 64) { mrowS[tid] = -1e30f; lrowS[tid] = 0.0f; }
    for (int i = tid; i < 64*SH2/2; i += 512) ((uint32_t*)Bnd)[i] = 0u;

    // stage Q into PhQh
    *(uint4*)&PhQh[rr*SH + cc] =
        *(const uint4*)(g_qh + (((size_t)((b*LL + q0 + rr)*HH + h)) << 6) + cc);

    uint2 pM = *(const uint2*)(g_mask8 + ((size_t)b*LL + q0 + srow)*LL + scol);

    __syncthreads();

    // Q fragments in registers (PhQh free for probs afterward)
    uint32_t qa[4][4];
    #pragma unroll
    for (int ks = 0; ks < 4; ks++) {
        qa[ks][0] = ldh2(&PhQh[ r0    *SH + ks*16 + 2*t    ]);
        qa[ks][1] = ldh2(&PhQh[(r0+8) *SH + ks*16 + 2*t    ]);
        qa[ks][2] = ldh2(&PhQh[ r0    *SH + ks*16 + 2*t + 8]);
        qa[ks][3] = ldh2(&PhQh[(r0+8) *SH + ks*16 + 2*t + 8]);
    }

    float oacc[2][4] = {};
    uint4 pK, pV;
    bool  havePf = false;

    for (int kt = 0; kt < 16; kt++) {
        const int k0 = kt * 64;
        const int d0 = k0 - q0;
        const int pb = ((kt + 1) & 1) << 6;   // phys base of NEW rel block
        const int kb = (kt & 1) << 6;         // ring rotation for lookups

        // ---- clear previous tile's band entries ----
        if (kt > 0) {
            const int kbp = ((kt - 1) & 1) << 6;
            const __half hz = __float2half_rn(0.0f);
            #pragma unroll
            for (int ccx = 0; ccx < 8; ccx++)
                Bnd[srow*SH2 + ((scol + ccx - srow + 63 + kbp) & 127)] = hz;
        }

        // ---- staging K/V (prefetched) ----
        if (!havePf) {
            *(uint4*)&Kh[rr*SH + cc] =
                *(const uint4*)(g_kh + (((size_t)((b*LL + k0 + rr)*HH + h)) << 6) + cc);
            {
                uint4 v0 = *(const uint4*)(g_vh + (((size_t)((b*LL + k0 + kp)*HH + h)) << 6) + dg*8);
                const __half* vh = (const __half*)&v0;
                #pragma unroll
                for (int j = 0; j < 8; j++) Vt[(dg*8 + j)*SH + kp] = vh[j];
            }
        } else {
            *(uint4*)&Kh[rr*SH + cc] = pK;
            const __half* vh = (const __half*)&pV;
            #pragma unroll
            for (int j = 0; j < 8; j++) Vt[(dg*8 + j)*SH + kp] = vh[j];
        }
        // ---- staging rel tables (direct, L2-resident) ----
        {
            // Tkw: new block rows (kt==0 handles block 0 here, block 1 later)
            int jj0 = (kt == 0) ? 0 : 64;
            int df = clampdiff(d0 + jj0 + rr - 63);
            *(uint4*)&Tkw[rr*SH + cc] =
                *(const uint4*)(g_relk_h + ((size_t)(df + MAXREL) << 6) + cc);
        }
        {
            int jj0 = (kt == 0) ? 0 : 64;
            int pbX = (kt == 0) ? 0 : pb;
            int df = clampdiff(d0 + jj0 + kp - 63);
            uint4 v0 = *(const uint4*)(g_relv_h + ((size_t)(df + MAXREL) << 6) + dg*8);
            const __half* vh = (const __half*)&v0;
            #pragma unroll
            for (int j = 0; j < 8; j++) Tvwt[(dg*8 + j)*SH2 + pbX + kp] = vh[j];
            if (kt == 0) {
                int df2 = clampdiff(d0 + 64 + kp - 63);
                uint4 v1 = *(const uint4*)(g_relv_h + ((size_t)(df2 + MAXREL) << 6) + dg*8);
                const __half* vh1 = (const __half*)&v1;
                #pragma unroll
                for (int j = 0; j < 8; j++) Tvwt[(dg*8 + j)*SH2 + 64 + kp] = vh1[j];
            }
        }
        __syncthreads();

        // ---- prefetch K/V for tile kt+1 ----
        if (kt < 15) {
            const int k0n = k0 + 64;
            pK = *(const uint4*)(g_kh + (((size_t)((b*LL + k0n + rr)*HH + h)) << 6) + cc);
            pV = *(const uint4*)(g_vh + (((size_t)((b*LL + k0n + kp)*HH + h)) << 6) + dg*8);
            havePf = true;
        }

        // ---- GEMM1a: QK scores ----
        #pragma unroll
        for (int nt = 0; nt < 2; nt++) {
            const int n0 = wc*16 + nt*8;
            const __half* Bb = Kh + (n0 + g)*SH;
            float c0 = 0.f, c1 = 0.f, c2 = 0.f, c3 = 0.f;
            #pragma unroll
            for (int ks = 0; ks < 4; ks++) {
                uint32_t b0 = ldh2(Bb + ks*16 + 2*t);
                uint32_t b1 = ldh2(Bb + ks*16 + 2*t + 8);
                MMA_F16(c0, c1, c2, c3, qa[ks][0], qa[ks][1], qa[ks][2], qa[ks][3], b0, b1);
            }
            *(float2*)&SQK[ r0   *SQ + n0 + 2*t] = make_float2(c0, c1);
            *(float2*)&SQK[(r0+8)*SQ + n0 + 2*t] = make_float2(c2, c3);
        }
        // ---- GEMM1b: rel scores for NEW block -> SrelH (fp16) ----
        {
            const int pbX = (kt == 0) ? 0 : pb;
            #pragma unroll
            for (int nt = 0; nt < 2; nt++) {
                const int nn = wc*16 + nt*8;
                const __half* Bb = Tkw + (nn + g)*SH;
                float c0 = 0.f, c1 = 0.f, c2 = 0.f, c3 = 0.f;
                #pragma unroll
                for (int ks = 0; ks < 4; ks++) {
                    uint32_t b0 = ldh2(Bb + ks*16 + 2*t);
                    uint32_t b1 = ldh2(Bb + ks*16 + 2*t + 8);
                    MMA_F16(c0, c1, c2, c3, qa[ks][0], qa[ks][1], qa[ks][2], qa[ks][3], b0, b1);
                }
                __half2 h01 = __floats2half2_rn(c0, c1);
                __half2 h23 = __floats2half2_rn(c2, c3);
                *(uint32_t*)&SrelH[ r0   *SH2 + pbX + nn + 2*t] = *(uint32_t*)&h01;
                *(uint32_t*)&SrelH[(r0+8)*SH2 + pbX + nn + 2*t] = *(uint32_t*)&h23;
            }
        }
        // ---- tile 0 extra pass: rel block 1 ----
        if (kt == 0) {
            __syncthreads();
            {
                int df = clampdiff(d0 + 64 + rr - 63);
                *(uint4*)&Tkw[rr*SH + cc] =
                    *(const uint4*)(g_relk_h + ((size_t)(df + MAXREL) << 6) + cc);
            }
            __syncthreads();
            #pragma unroll
            for (int nt = 0; nt < 2; nt++) {
                const int nn = wc*16 + nt*8;
                const __half* Bb = Tkw + (nn + g)*SH;
                float c0 = 0.f, c1 = 0.f, c2 = 0.f, c3 = 0.f;
                #pragma unroll
                for (int ks = 0; ks < 4; ks++) {
                    uint32_t b0 = ldh2(Bb + ks*16 + 2*t);
                    uint32_t b1 = ldh2(Bb + ks*16 + 2*t + 8);
                    MMA_F16(c0, c1, c2, c3, qa[ks][0], qa[ks][1], qa[ks][2], qa[ks][3], b0, b1);
                }
                __half2 h01 = __floats2half2_rn(c0, c1);
                __half2 h23 = __floats2half2_rn(c2, c3);
                *(uint32_t*)&SrelH[ r0   *SH2 + 64 + nn + 2*t] = *(uint32_t*)&h01;
                *(uint32_t*)&SrelH[(r0+8)*SH2 + 64 + nn + 2*t] = *(uint32_t*)&h23;
            }
        }
        __syncthreads();

        // ---- softmax: one row per 8 threads, 8 cols per thread ----
        {
            float4 s4a = *(const float4*)&SQK[srow*SQ + scol];
            float4 s4b = *(const float4*)&SQK[srow*SQ + scol + 4];
            float sv[8];
            sv[0] = (pM.x & 0x000000ffu) ? s4a.x : -1e20f;
            sv[1] = (pM.x & 0x0000ff00u) ? s4a.y : -1e20f;
            sv[2] = (pM.x & 0x00ff0000u) ? s4a.z : -1e20f;
            sv[3] = (pM.x & 0xff000000u) ? s4a.w : -1e20f;
            sv[4] = (pM.y & 0x000000ffu) ? s4b.x : -1e20f;
            sv[5] = (pM.y & 0x0000ff00u) ? s4b.y : -1e20f;
            sv[6] = (pM.y & 0x00ff0000u) ? s4b.z : -1e20f;
            sv[7] = (pM.y & 0xff000000u) ? s4b.w : -1e20f;
            #pragma unroll
            for (int ccx = 0; ccx < 8; ccx++) {
                int c = scol + ccx;
                float rel = __half2float(SrelH[srow*SH2 + ((c - srow + 63 + kb) & 127)]);
                sv[ccx] = (sv[ccx] + rel) * 0.125f;
            }
            float rm = sv[0];
            #pragma unroll
            for (int ccx = 1; ccx < 8; ccx++) rm = fmaxf(rm, sv[ccx]);
            #pragma unroll
            for (int o = 1; o < 8; o <<= 1)
                rm = fmaxf(rm, __shfl_xor_sync(0xffffffffu, rm, o));
            float mold = mrowS[srow];
            float mn = fmaxf(mold, rm);
            float csc = __expf(mold - mn);
            float p[8], ls = 0.f;
            #pragma unroll
            for (int ccx = 0; ccx < 8; ccx++) { p[ccx] = __expf(sv[ccx] - mn); ls += p[ccx]; }
            #pragma unroll
            for (int o = 1; o < 8; o <<= 1)
                ls += __shfl_xor_sync(0xffffffffu, ls, o);
            if ((tid & 7) == 0) {
                mrowS[srow] = mn;
                cscS[srow]  = csc;
                lrowS[srow] = lrowS[srow]*csc + ls;
            }
            uint4 ph;
            {
                __half2 h0 = __floats2half2_rn(p[0], p[1]);
                __half2 h1 = __floats2half2_rn(p[2], p[3]);
                __half2 h2 = __floats2half2_rn(p[4], p[5]);
                __half2 h3 = __floats2half2_rn(p[6], p[7]);
                ph.x = *(uint32_t*)&h0; ph.y = *(uint32_t*)&h1;
                ph.z = *(uint32_t*)&h2; ph.w = *(uint32_t*)&h3;
            }
            *(uint4*)&PhQh[srow*SH + scol] = ph;
            #pragma unroll
            for (int ccx = 0; ccx < 8; ccx++) {
                int c = scol + ccx;
                Bnd[srow*SH2 + ((c - srow + 63 + kb) & 127)] = __float2half_rn(p[ccx]);
            }
        }
        if (kt < 15)
            pM = *(const uint2*)(g_mask8 + ((size_t)b*LL + q0 + srow)*LL + (k0 + 64) + scol);
        __syncthreads();

        // ---- GEMM2: oacc = csc*oacc + P@V + Pband@Tvw ----
        {
            const float f0 = cscS[r0], f1 = cscS[r0+8];
            #pragma unroll
            for (int nt = 0; nt < 2; nt++) {
                oacc[nt][0] *= f0; oacc[nt][1] *= f0;
                oacc[nt][2] *= f1; oacc[nt][3] *= f1;
            }
            #pragma unroll
            for (int ks = 0; ks < 4; ks++) {
                uint32_t a0 = ldh2(&PhQh[ r0   *SH + ks*16 + 2*t    ]);
                uint32_t a1 = ldh2(&PhQh[(r0+8)*SH + ks*16 + 2*t    ]);
                uint32_t a2 = ldh2(&PhQh[ r0   *SH + ks*16 + 2*t + 8]);
                uint32_t a3 = ldh2(&PhQh[(r0+8)*SH + ks*16 + 2*t + 8]);
                #pragma unroll
                for (int nt = 0; nt < 2; nt++) {
                    const __half* Bb = Vt + (wc*16 + nt*8 + g)*SH;
                    uint32_t b0 = ldh2(Bb + ks*16 + 2*t);
                    uint32_t b1 = ldh2(Bb + ks*16 + 2*t + 8);
                    MMA_F16(oacc[nt][0], oacc[nt][1], oacc[nt][2], oacc[nt][3],
                            a0, a1, a2, a3, b0, b1);
                }
            }
            #pragma unroll
            for (int ks = 0; ks < 8; ks++) {
                uint32_t a0 = ldh2(&Bnd[ r0   *SH2 + ks*16 + 2*t    ]);
                uint32_t a1 = ldh2(&Bnd[(r0+8)*SH2 + ks*16 + 2*t    ]);
                uint32_t a2 = ldh2(&Bnd[ r0   *SH2 + ks*16 + 2*t + 8]);
                uint32_t a3 = ldh2(&Bnd[(r0+8)*SH2 + ks*16 + 2*t + 8]);
                #pragma unroll
                for (int nt = 0; nt < 2; nt++) {
                    const __half* Bb = Tvwt + (wc*16 + nt*8 + g)*SH2;
                    uint32_t b0 = ldh2(Bb + ks*16 + 2*t);
                    uint32_t b1 = ldh2(Bb + ks*16 + 2*t + 8);
                    MMA_F16(oacc[nt][0], oacc[nt][1], oacc[nt][2], oacc[nt][3],
                            a0, a1, a2, a3, b0, b1);
                }
            }
        }
        __syncthreads();
    }

    // ---- epilogue ----
    {
        const float l0 = 1.0f / lrowS[r0];
        const float l1 = 1.0f / lrowS[r0 + 8];
        const size_t base0 = (((size_t)((b*LL + q0 + r0    )*HH + h)) << 6);
        const size_t base1 = (((size_t)((b*LL + q0 + r0 + 8)*HH + h)) << 6);
        #pragma unroll
        for (int nt = 0; nt < 2; nt++) {
            int c = wc*16 + nt*8 + 2*t;
            __half2 h0 = __floats2half2_rn(oacc[nt][0]*l0, oacc[nt][1]*l0);
            __half2 h1 = __floats2half2_rn(oacc[nt][2]*l1, oacc[nt][3]*l1);
            *(uint32_t*)(g_ctx + base0 + c) = *(uint32_t*)&h0;
            *(uint32_t*)(g_ctx + base1 + c) = *(uint32_t*)&h1;
        }
    }
}

// ---------------------------------------------------------------------------
// Final FC, fp16 mma, 128x128 tiles, 512 threads, 2 CTAs/SM, reg prefetch.
// ---------------------------------------------------------------------------
__global__ __launch_bounds__(512, 2) void fc_kernel(
    const float* __restrict__ bfc, float* __restrict__ out)
{
    __shared__ __half Xs[128*SH];
    __shared__ __half Ws[128*SH];

    const int tid  = threadIdx.x;
    const int warp = tid >> 5, lane = tid & 31;
    const int g = lane >> 2, t = lane & 3;
    const int wr = warp >> 2, wc = warp & 3;
    const size_t r0 = (size_t)blockIdx.x * 128;
    const size_t n0 = (size_t)blockIdx.y * 128;

    const int rrA = tid >> 3,         ccA = (tid & 7) << 3;
    const int rrB = (tid + 512) >> 3, ccB = ((tid + 512) & 7) << 3;

    float oacc[2][4][4] = {};
    uint4 pX[2], pW[2];

    *(uint4*)&Xs[rrA*SH + ccA] = *(const uint4*)(g_ctx   + (r0 + rrA)*EMBN + ccA);
    *(uint4*)&Xs[rrB*SH + ccB] = *(const uint4*)(g_ctx   + (r0 + rrB)*EMBN + ccB);
    *(uint4*)&Ws[rrA*SH + ccA] = *(const uint4*)(g_Wfc_h + (n0 + rrA)*EMBN + ccA);
    *(uint4*)&Ws[rrB*SH + ccB] = *(const uint4*)(g_Wfc_h + (n0 + rrB)*EMBN + ccB);

    for (int e = 0; e < 16; e++) {
        __syncthreads();
        if (e < 15) {
            const int e0n = (e + 1) * 64;
            pX[0] = *(const uint4*)(g_ctx   + (r0 + rrA)*EMBN + e0n + ccA);
            pX[1] = *(const uint4*)(g_ctx   + (r0 + rrB)*EMBN + e0n + ccB);
            pW[0] = *(const uint4*)(g_Wfc_h + (n0 + rrA)*EMBN + e0n + ccA);
            pW[1] = *(const uint4*)(g_Wfc_h + (n0 + rrB)*EMBN + e0n + ccB);
        }
        #pragma unroll
        for (int ks = 0; ks < 4; ks++) {
            uint32_t a[2][4];
            #pragma unroll
            for (int mi = 0; mi < 2; mi++) {
                int ar = wr*32 + mi*16 + g;
                a[mi][0] = ldh2(&Xs[ ar   *SH + ks*16 + 2*t    ]);
                a[mi][1] = ldh2(&Xs[(ar+8)*SH + ks*16 + 2*t    ]);
                a[mi][2] = ldh2(&Xs[ ar   *SH + ks*16 + 2*t + 8]);
                a[mi][3] = ldh2(&Xs[(ar+8)*SH + ks*16 + 2*t + 8]);
            }
            #pragma unroll
            for (int nt = 0; nt < 4; nt++) {
                const __half* Bb = Ws + (wc*32 + nt*8 + g)*SH;
                uint32_t b0 = ldh2(Bb + ks*16 + 2*t);
                uint32_t b1 = ldh2(Bb + ks*16 + 2*t + 8);
                #pragma unroll
                for (int mi = 0; mi < 2; mi++)
                    MMA_F16(oacc[mi][nt][0], oacc[mi][nt][1], oacc[mi][nt][2], oacc[mi][nt][3],
                            a[mi][0], a[mi][1], a[mi][2], a[mi][3], b0, b1);
            }
        }
        __syncthreads();
        if (e < 15) {
            *(uint4*)&Xs[rrA*SH + ccA] = pX[0];
            *(uint4*)&Xs[rrB*SH + ccB] = pX[1];
            *(uint4*)&Ws[rrA*SH + ccA] = pW[0];
            *(uint4*)&Ws[rrB*SH + ccB] = pW[1];
        }
    }

    #pragma unroll
    for (int mi = 0; mi < 2; mi++) {
        size_t ra = r0 + wr*32 + mi*16 + g;
        #pragma unroll
        for (int nt = 0; nt < 4; nt++) {
            size_t c = n0 + wc*32 + nt*8 + 2*t;
            float bv0 = bfc[c], bv1 = bfc[c+1];
            *(float2*)(out + ra*EMBN + c) =
                make_float2(oacc[mi][nt][0] + bv0, oacc[mi][nt][1] + bv1);
            *(float2*)(out + (ra+8)*EMBN + c) =
                make_float2(oacc[mi][nt][2] + bv0, oacc[mi][nt][3] + bv1);
        }
    }
}

// ---------------------------------------------------------------------------
extern "C" void kernel_launch(void* const* d_in, const int* in_sizes, int n_in,
                              void* d_out, int out_size)
{
    const float* query = (const float*)d_in[0];
    const float* key_  = (const float*)d_in[1];
    const float* value = (const float*)d_in[2];
    const int*   mask  = (const int*)d_in[3];
    const float* Wq = (const float*)d_in[4];
    const float* bq = (const float*)d_in[5];
    const float* Wk = (const float*)d_in[6];
    const float* bk = (const float*)d_in[7];
    const float* Wv = (const float*)d_in[8];
    const float* bv = (const float*)d_in[9];
    const float* Wfc = (const float*)d_in[10];
    const float* bfc = (const float*)d_in[11];
    const float* relk = (const float*)d_in[12];
    const float* relv = (const float*)d_in[13];
    float* out = (float*)d_out;

    cudaFuncSetAttribute(attn_kernel, cudaFuncAttributeMaxDynamicSharedMemorySize, ATT_SMEM_BYTES);

    pre_kernel<<<dim3(1024, 4, 1), 256>>>(query, key_, value, Wq, bq, Wk, bk, Wv, bv,
                                          relk, relv, Wfc, mask);
    attn_kernel<<<dim3(16, 16, 4), 512, ATT_SMEM_BYTES>>>();
    fc_kernel<<<dim3(32, 8, 1), 512>>>(bfc, out);
}

// round 7
// speedup vs baseline: 1.3202x; 1.3202x over previous
#include <cuda_runtime.h>
#include <cuda_fp16.h>
#include <cstdint>
#include <cstddef>

#define BB   4
#define LL   1024
#define HH   16
#define DD   64
#define EMBN 1024
#define MAXREL 512
#define NREL (2*MAXREL + 1)

#define SH   72    // half stride, 64-wide tiles  (36 words == 4 mod 32)
#define SH2  136   // half stride, 128-wide tiles (68 words == 4 mod 32)
#define SQ   68    // float stride for SQK
#define SBW  104   // half stride, band buffer (52 words == 20 mod 32)

// Scratch (allocation-free rule: device globals)
__device__ __half g_qh [BB*LL*HH*DD];
__device__ __half g_kh [BB*LL*HH*DD];
__device__ __half g_vh [BB*LL*HH*DD];
__device__ __half g_ctx[BB*LL*HH*DD];
__device__ __half g_relk_h[NREL*DD];
__device__ __half g_relv_h[NREL*DD];
__device__ __half g_Wfc_h[EMBN*EMBN];
__device__ unsigned char g_mask8[BB*LL*LL];

// ---------------------------------------------------------------------------
#define MMA_F16(d0,d1,d2,d3,a0,a1,a2,a3,b0,b1)                               \
    asm volatile("mma.sync.aligned.m16n8k16.row.col.f32.f16.f16.f32 "        \
                 "{%0,%1,%2,%3}, {%4,%5,%6,%7}, {%8,%9}, {%0,%1,%2,%3};"     \
                 : "+f"(d0), "+f"(d1), "+f"(d2), "+f"(d3)                    \
                 : "r"(a0), "r"(a1), "r"(a2), "r"(a3), "r"(b0), "r"(b1))

#define LDSM_X4(r0,r1,r2,r3,addr)                                            \
    asm volatile("ldmatrix.sync.aligned.m8n8.x4.shared.b16 {%0,%1,%2,%3}, [%4];" \
                 : "=r"(r0), "=r"(r1), "=r"(r2), "=r"(r3) : "r"(addr))

__device__ __forceinline__ uint32_t ldh2(const __half* p) {
    return *(const uint32_t*)p;
}
__device__ __forceinline__ uint32_t s2u(const void* p) {
    return (uint32_t)__cvta_generic_to_shared(p);
}
__device__ __forceinline__ int clampdiff(int d) {
    return d < -MAXREL ? -MAXREL : (d > MAXREL ? MAXREL : d);
}

// ---------------------------------------------------------------------------
// Pre: projections (y = 0..2) + fp16 constant conversion / mask pack (y = 3)
// ---------------------------------------------------------------------------
#define SA 68
__global__ __launch_bounds__(256) void pre_kernel(
    const float* __restrict__ query, const float* __restrict__ key_, const float* __restrict__ value,
    const float* __restrict__ Wq, const float* __restrict__ bq,
    const float* __restrict__ Wk, const float* __restrict__ bk,
    const float* __restrict__ Wv, const float* __restrict__ bv,
    const float* __restrict__ relk, const float* __restrict__ relv,
    const float* __restrict__ Wfc,  const int* __restrict__ mask)
{
    const int tid = threadIdx.x;

    if (blockIdx.y == 3) {
        const int stride = 1024 * 256;
        const int base = blockIdx.x * 256 + tid;
        for (int i = base; i < NREL*DD; i += stride) {
            g_relk_h[i] = __float2half_rn(relk[i]);
            g_relv_h[i] = __float2half_rn(relv[i]);
        }
        for (int i = base; i < EMBN*EMBN; i += stride)
            g_Wfc_h[i] = __float2half_rn(Wfc[i]);
        for (int i = base; i < BB*LL*LL; i += stride)
            g_mask8[i] = (unsigned char)(mask[i] != 0);
        return;
    }

    __shared__ float Xs[64*SA];
    __shared__ float Ws[64*SA];
    __shared__ float bs[64];

    const float* X; const float* W; const float* bias; __half* out;
    if (blockIdx.y == 0)      { X = query; W = Wq; bias = bq; out = g_qh; }
    else if (blockIdx.y == 1) { X = key_;  W = Wk; bias = bk; out = g_kh; }
    else                      { X = value; W = Wv; bias = bv; out = g_vh; }

    const size_t r0 = (size_t)blockIdx.x * 64;

    #pragma unroll
    for (int t = 0; t < 4; t++) {
        int idx = tid + t*256;
        int rr = idx >> 4, cc = (idx & 15) << 2;
        *(float4*)&Xs[rr*SA + cc] = *(const float4*)(X + (r0 + rr)*64 + cc);
        *(float4*)&Ws[rr*SA + cc] = *(const float4*)(W + (size_t)rr*64 + cc);
    }
    if (tid < 64) bs[tid] = bias[tid];
    __syncthreads();

    const int ty = tid >> 4, tx = tid & 15;
    float acc[4][4] = {};
    for (int e = 0; e < 64; e += 4) {
        float4 a[4], bb[4];
        #pragma unroll
        for (int ii = 0; ii < 4; ii++) a[ii]  = *(const float4*)&Xs[(ty + 16*ii)*SA + e];
        #pragma unroll
        for (int jj = 0; jj < 4; jj++) bb[jj] = *(const float4*)&Ws[(tx + 16*jj)*SA + e];
        #pragma unroll
        for (int ii = 0; ii < 4; ii++)
            #pragma unroll
            for (int jj = 0; jj < 4; jj++)
                acc[ii][jj] += a[ii].x*bb[jj].x + a[ii].y*bb[jj].y
                             + a[ii].z*bb[jj].z + a[ii].w*bb[jj].w;
    }
    #pragma unroll
    for (int ii = 0; ii < 4; ii++) {
        int i = ty + 16*ii;
        #pragma unroll
        for (int jj = 0; jj < 4; jj++) {
            int d = tx + 16*jj;
            out[(r0 + i)*64 + d] = __float2half_rn(acc[ii][jj] + bs[d]);
        }
    }
}

// ---------------------------------------------------------------------------
// Flash attention + relative bias. 256 threads = 8 warps (2 m-groups x 4 n).
// ldmatrix fragment loads, per-warp-group shifted band (K=96).
// ---------------------------------------------------------------------------
#define ATT_F_WORDS (64*SQ + 192)
#define ATT_H_WORDS (64*SH2 + 3*64*SH + 64*SH + 64*SH2 + 64*SBW)
#define ATT_SMEM_BYTES (ATT_F_WORDS*4 + ATT_H_WORDS*2)

__global__ __launch_bounds__(256, 2) void attn_kernel()
{
    extern __shared__ float smf[];
    float*  SQK   = smf;                      // 64 x SQ   fp32 QK scores
    float*  mrowS = SQK   + 64*SQ;            // 64
    float*  lrowS = mrowS + 64;               // 64
    float*  cscS  = lrowS + 64;               // 64
    __half* SrelH = (__half*)(cscS + 64);     // 64 x SH2  rel-score ring
    __half* Kh    = SrelH + 64*SH2;           // 64 x SH   [kpos][e]
    __half* Vt    = Kh    + 64*SH;            // 64 x SH   [d][kpos]
    __half* PhQh  = Vt    + 64*SH;            // 64 x SH   Q then probs [q][j]
    __half* Tkw   = PhQh  + 64*SH;            // 64 x SH   new rel_k block [j][e]
    __half* Tvwt  = Tkw   + 64*SH;            // 64 x SH2  rel_v ring [d][slot]
    __half* Bw    = Tvwt  + 64*SH2;           // 64 x SBW  dense band [q][dd]

    const int b  = blockIdx.z;
    const int h  = blockIdx.y;
    const int q0 = blockIdx.x * 64;
    const int tid  = threadIdx.x;
    const int warp = tid >> 5, lane = tid & 31;
    const int g = lane >> 2, t = lane & 3;
    const int wr = warp >> 2, wc = warp & 3;   // 2 m-groups x 4 n-groups
    const int l7 = lane & 7, l15 = lane & 15;
    const int lq8 = (lane >> 3) << 3;          // 0,8,16,24
    const int lq16 = (lane >> 4) << 3;         // 0,8

    const int srow = tid >> 2;                 // softmax: 4 threads/row
    const int scol = (tid & 3) << 4;           // 16 cols/thread

    const int rrA = tid >> 3, ccA = (tid & 7) << 3;   // staging rows 0..31
    const int kp = tid & 63, dg = tid >> 6;           // transpose: 16 d's/thread

    if (tid < 64) { mrowS[tid] = -1e30f; lrowS[tid] = 0.0f; }

    // stage Q
    *(uint4*)&PhQh[ rrA      *SH + ccA] =
        *(const uint4*)(g_qh + (((size_t)((b*LL + q0 + rrA     )*HH + h)) << 6) + ccA);
    *(uint4*)&PhQh[(rrA + 32)*SH + ccA] =
        *(const uint4*)(g_qh + (((size_t)((b*LL + q0 + rrA + 32)*HH + h)) << 6) + ccA);

    uint4 pM = *(const uint4*)(g_mask8 + ((size_t)b*LL + q0 + srow)*LL + scol);
    __syncthreads();

    // Q A-fragments in registers: qa[mt][ks][4]
    uint32_t qa[2][4][4];
    #pragma unroll
    for (int mt = 0; mt < 2; mt++)
        #pragma unroll
        for (int ks = 0; ks < 4; ks++) {
            uint32_t ad = s2u(PhQh + (wr*32 + mt*16 + l15)*SH + ks*16 + lq16);
            LDSM_X4(qa[mt][ks][0], qa[mt][ks][1], qa[mt][ks][2], qa[mt][ks][3], ad);
        }

    float oacc[2][2][4] = {};   // [mt][nt][4]
    uint4 pK, pV0, pV1;
    bool  havePf = false;

    for (int kt = 0; kt < 16; kt++) {
        const int k0 = kt * 64;
        const int d0 = k0 - q0;
        const int pb = ((kt + 1) & 1) << 6;
        const int kb = (kt & 1) << 6;

        // ---- clear dense band buffer (read by prev GEMM2, synced) ----
        {
            const uint4 z = make_uint4(0,0,0,0);
            #pragma unroll
            for (int i = 0; i < 4; i++) {
                int idx = tid + i*256;
                if (idx < 832) ((uint4*)Bw)[idx] = z;
            }
        }

        // ---- staging K/V ----
        if (!havePf) {
            *(uint4*)&Kh[ rrA      *SH + ccA] =
                *(const uint4*)(g_kh + (((size_t)((b*LL + k0 + rrA     )*HH + h)) << 6) + ccA);
            *(uint4*)&Kh[(rrA + 32)*SH + ccA] =
                *(const uint4*)(g_kh + (((size_t)((b*LL + k0 + rrA + 32)*HH + h)) << 6) + ccA);
            pV0 = *(const uint4*)(g_vh + (((size_t)((b*LL + k0 + kp)*HH + h)) << 6) + dg*16);
            pV1 = *(const uint4*)(g_vh + (((size_t)((b*LL + k0 + kp)*HH + h)) << 6) + dg*16 + 8);
        } else {
            *(uint4*)&Kh[rrA*SH + ccA] = pK;
            // second half of K was prefetched into pV-free slot? no: restage from L2
            *(uint4*)&Kh[(rrA + 32)*SH + ccA] =
                *(const uint4*)(g_kh + (((size_t)((b*LL + k0 + rrA + 32)*HH + h)) << 6) + ccA);
        }
        {
            const __half* v0 = (const __half*)&pV0;
            const __half* v1 = (const __half*)&pV1;
            #pragma unroll
            for (int j = 0; j < 8; j++) {
                Vt[(dg*16 + j    )*SH + kp] = v0[j];
                Vt[(dg*16 + j + 8)*SH + kp] = v1[j];
            }
        }
        // ---- staging rel tables (direct, L2-resident) ----
        {
            const int jj0 = (kt == 0) ? 0 : 64;
            const int pbX = (kt == 0) ? 0 : pb;
            int dfA = clampdiff(d0 + jj0 + rrA - 63);
            int dfB = clampdiff(d0 + jj0 + rrA + 32 - 63);
            *(uint4*)&Tkw[ rrA      *SH + ccA] = *(const uint4*)(g_relk_h + ((size_t)(dfA + MAXREL) << 6) + ccA);
            *(uint4*)&Tkw[(rrA + 32)*SH + ccA] = *(const uint4*)(g_relk_h + ((size_t)(dfB + MAXREL) << 6) + ccA);
            int df = clampdiff(d0 + jj0 + kp - 63);
            uint4 r0v = *(const uint4*)(g_relv_h + ((size_t)(df + MAXREL) << 6) + dg*16);
            uint4 r1v = *(const uint4*)(g_relv_h + ((size_t)(df + MAXREL) << 6) + dg*16 + 8);
            const __half* h0 = (const __half*)&r0v;
            const __half* h1 = (const __half*)&r1v;
            #pragma unroll
            for (int j = 0; j < 8; j++) {
                Tvwt[(dg*16 + j    )*SH2 + pbX + kp] = h0[j];
                Tvwt[(dg*16 + j + 8)*SH2 + pbX + kp] = h1[j];
            }
            if (kt == 0) {
                int df2 = clampdiff(d0 + 64 + kp - 63);
                uint4 r2v = *(const uint4*)(g_relv_h + ((size_t)(df2 + MAXREL) << 6) + dg*16);
                uint4 r3v = *(const uint4*)(g_relv_h + ((size_t)(df2 + MAXREL) << 6) + dg*16 + 8);
                const __half* h2 = (const __half*)&r2v;
                const __half* h3 = (const __half*)&r3v;
                #pragma unroll
                for (int j = 0; j < 8; j++) {
                    Tvwt[(dg*16 + j    )*SH2 + 64 + kp] = h2[j];
                    Tvwt[(dg*16 + j + 8)*SH2 + 64 + kp] = h3[j];
                }
            }
        }
        __syncthreads();

        // ---- prefetch K/V for tile kt+1 ----
        if (kt < 15) {
            const int k0n = k0 + 64;
            pK  = *(const uint4*)(g_kh + (((size_t)((b*LL + k0n + rrA)*HH + h)) << 6) + ccA);
            pV0 = *(const uint4*)(g_vh + (((size_t)((b*LL + k0n + kp )*HH + h)) << 6) + dg*16);
            pV1 = *(const uint4*)(g_vh + (((size_t)((b*LL + k0n + kp )*HH + h)) << 6) + dg*16 + 8);
            havePf = true;
        }

        // ---- GEMM1a: QK scores (m32 x n16 per warp) ----
        #pragma unroll
        for (int nt = 0; nt < 2; nt++) {
            float c0[4] = {0,0,0,0}, c1[4] = {0,0,0,0};
            #pragma unroll
            for (int ksp = 0; ksp < 2; ksp++) {
                uint32_t b0,b1,b2,b3;
                uint32_t ad = s2u(Kh + (wc*16 + nt*8 + l7)*SH + ksp*32 + lq8);
                LDSM_X4(b0,b1,b2,b3, ad);
                MMA_F16(c0[0],c0[1],c0[2],c0[3], qa[0][2*ksp  ][0],qa[0][2*ksp  ][1],qa[0][2*ksp  ][2],qa[0][2*ksp  ][3], b0,b1);
                MMA_F16(c1[0],c1[1],c1[2],c1[3], qa[1][2*ksp  ][0],qa[1][2*ksp  ][1],qa[1][2*ksp  ][2],qa[1][2*ksp  ][3], b0,b1);
                MMA_F16(c0[0],c0[1],c0[2],c0[3], qa[0][2*ksp+1][0],qa[0][2*ksp+1][1],qa[0][2*ksp+1][2],qa[0][2*ksp+1][3], b2,b3);
                MMA_F16(c1[0],c1[1],c1[2],c1[3], qa[1][2*ksp+1][0],qa[1][2*ksp+1][1],qa[1][2*ksp+1][2],qa[1][2*ksp+1][3], b2,b3);
            }
            const int colb = wc*16 + nt*8 + 2*t;
            *(float2*)&SQK[(wr*32      + g)*SQ + colb] = make_float2(c0[0],c0[1]);
            *(float2*)&SQK[(wr*32 +  8 + g)*SQ + colb] = make_float2(c0[2],c0[3]);
            *(float2*)&SQK[(wr*32 + 16 + g)*SQ + colb] = make_float2(c1[0],c1[1]);
            *(float2*)&SQK[(wr*32 + 24 + g)*SQ + colb] = make_float2(c1[2],c1[3]);
        }
        // ---- GEMM1b: rel scores for NEW block -> SrelH ----
        {
            const int pbX = (kt == 0) ? 0 : pb;
            #pragma unroll
            for (int nt = 0; nt < 2; nt++) {
                float c0[4] = {0,0,0,0}, c1[4] = {0,0,0,0};
                #pragma unroll
                for (int ksp = 0; ksp < 2; ksp++) {
                    uint32_t b0,b1,b2,b3;
                    uint32_t ad = s2u(Tkw + (wc*16 + nt*8 + l7)*SH + ksp*32 + lq8);
                    LDSM_X4(b0,b1,b2,b3, ad);
                    MMA_F16(c0[0],c0[1],c0[2],c0[3], qa[0][2*ksp  ][0],qa[0][2*ksp  ][1],qa[0][2*ksp  ][2],qa[0][2*ksp  ][3], b0,b1);
                    MMA_F16(c1[0],c1[1],c1[2],c1[3], qa[1][2*ksp  ][0],qa[1][2*ksp  ][1],qa[1][2*ksp  ][2],qa[1][2*ksp  ][3], b0,b1);
                    MMA_F16(c0[0],c0[1],c0[2],c0[3], qa[0][2*ksp+1][0],qa[0][2*ksp+1][1],qa[0][2*ksp+1][2],qa[0][2*ksp+1][3], b2,b3);
                    MMA_F16(c1[0],c1[1],c1[2],c1[3], qa[1][2*ksp+1][0],qa[1][2*ksp+1][1],qa[1][2*ksp+1][2],qa[1][2*ksp+1][3], b2,b3);
                }
                const int colb = pbX + wc*16 + nt*8 + 2*t;
                __half2 h0 = __floats2half2_rn(c0[0],c0[1]);
                __half2 h1 = __floats2half2_rn(c0[2],c0[3]);
                __half2 h2 = __floats2half2_rn(c1[0],c1[1]);
                __half2 h3 = __floats2half2_rn(c1[2],c1[3]);
                *(uint32_t*)&SrelH[(wr*32      + g)*SH2 + colb] = *(uint32_t*)&h0;
                *(uint32_t*)&SrelH[(wr*32 +  8 + g)*SH2 + colb] = *(uint32_t*)&h1;
                *(uint32_t*)&SrelH[(wr*32 + 16 + g)*SH2 + colb] = *(uint32_t*)&h2;
                *(uint32_t*)&SrelH[(wr*32 + 24 + g)*SH2 + colb] = *(uint32_t*)&h3;
            }
        }
        // ---- tile 0 extra rel block (dd 64..127) ----
        if (kt == 0) {
            __syncthreads();
            {
                int dfA = clampdiff(d0 + 64 + rrA - 63);
                int dfB = clampdiff(d0 + 64 + rrA + 32 - 63);
                *(uint4*)&Tkw[ rrA      *SH + ccA] = *(const uint4*)(g_relk_h + ((size_t)(dfA + MAXREL) << 6) + ccA);
                *(uint4*)&Tkw[(rrA + 32)*SH + ccA] = *(const uint4*)(g_relk_h + ((size_t)(dfB + MAXREL) << 6) + ccA);
            }
            __syncthreads();
            #pragma unroll
            for (int nt = 0; nt < 2; nt++) {
                float c0[4] = {0,0,0,0}, c1[4] = {0,0,0,0};
                #pragma unroll
                for (int ksp = 0; ksp < 2; ksp++) {
                    uint32_t b0,b1,b2,b3;
                    uint32_t ad = s2u(Tkw + (wc*16 + nt*8 + l7)*SH + ksp*32 + lq8);
                    LDSM_X4(b0,b1,b2,b3, ad);
                    MMA_F16(c0[0],c0[1],c0[2],c0[3], qa[0][2*ksp  ][0],qa[0][2*ksp  ][1],qa[0][2*ksp  ][2],qa[0][2*ksp  ][3], b0,b1);
                    MMA_F16(c1[0],c1[1],c1[2],c1[3], qa[1][2*ksp  ][0],qa[1][2*ksp  ][1],qa[1][2*ksp  ][2],qa[1][2*ksp  ][3], b0,b1);
                    MMA_F16(c0[0],c0[1],c0[2],c0[3], qa[0][2*ksp+1][0],qa[0][2*ksp+1][1],qa[0][2*ksp+1][2],qa[0][2*ksp+1][3], b2,b3);
                    MMA_F16(c1[0],c1[1],c1[2],c1[3], qa[1][2*ksp+1][0],qa[1][2*ksp+1][1],qa[1][2*ksp+1][2],qa[1][2*ksp+1][3], b2,b3);
                }
                const int colb = 64 + wc*16 + nt*8 + 2*t;
                __half2 h0 = __floats2half2_rn(c0[0],c0[1]);
                __half2 h1 = __floats2half2_rn(c0[2],c0[3]);
                __half2 h2 = __floats2half2_rn(c1[0],c1[1]);
                __half2 h3 = __floats2half2_rn(c1[2],c1[3]);
                *(uint32_t*)&SrelH[(wr*32      + g)*SH2 + colb] = *(uint32_t*)&h0;
                *(uint32_t*)&SrelH[(wr*32 +  8 + g)*SH2 + colb] = *(uint32_t*)&h1;
                *(uint32_t*)&SrelH[(wr*32 + 16 + g)*SH2 + colb] = *(uint32_t*)&h2;
                *(uint32_t*)&SrelH[(wr*32 + 24 + g)*SH2 + colb] = *(uint32_t*)&h3;
            }
        }
        __syncthreads();

        // ---- softmax: 4 threads/row, 16 cols each ----
        {
            float sv[16];
            *(float4*)&sv[0]  = *(const float4*)&SQK[srow*SQ + scol];
            *(float4*)&sv[4]  = *(const float4*)&SQK[srow*SQ + scol + 4];
            *(float4*)&sv[8]  = *(const float4*)&SQK[srow*SQ + scol + 8];
            *(float4*)&sv[12] = *(const float4*)&SQK[srow*SQ + scol + 12];
            uint32_t mw[4] = {pM.x, pM.y, pM.z, pM.w};
            #pragma unroll
            for (int i = 0; i < 16; i++) {
                uint32_t mb = (mw[i>>2] >> ((i & 3)*8)) & 0xffu;
                float rel = __half2float(SrelH[srow*SH2 + ((scol + i - srow + 63 + kb) & 127)]);
                float s = mb ? sv[i] : -1e20f;
                sv[i] = (s + rel) * 0.125f;
            }
            float rm = sv[0];
            #pragma unroll
            for (int i = 1; i < 16; i++) rm = fmaxf(rm, sv[i]);
            rm = fmaxf(rm, __shfl_xor_sync(0xffffffffu, rm, 1));
            rm = fmaxf(rm, __shfl_xor_sync(0xffffffffu, rm, 2));
            float mold = mrowS[srow];
            float mn = fmaxf(mold, rm);
            float csc = __expf(mold - mn);
            float p[16], ls = 0.f;
            #pragma unroll
            for (int i = 0; i < 16; i++) { p[i] = __expf(sv[i] - mn); ls += p[i]; }
            ls += __shfl_xor_sync(0xffffffffu, ls, 1);
            ls += __shfl_xor_sync(0xffffffffu, ls, 2);
            if ((tid & 3) == 0) {
                mrowS[srow] = mn;
                cscS[srow]  = csc;
                lrowS[srow] = lrowS[srow]*csc + ls;
            }
            // probs -> PhQh
            uint4 u0, u1;
            {
                __half2 a0 = __floats2half2_rn(p[0],p[1]),  a1 = __floats2half2_rn(p[2],p[3]);
                __half2 a2 = __floats2half2_rn(p[4],p[5]),  a3 = __floats2half2_rn(p[6],p[7]);
                __half2 a4 = __floats2half2_rn(p[8],p[9]),  a5 = __floats2half2_rn(p[10],p[11]);
                __half2 a6 = __floats2half2_rn(p[12],p[13]),a7 = __floats2half2_rn(p[14],p[15]);
                u0.x = *(uint32_t*)&a0; u0.y = *(uint32_t*)&a1; u0.z = *(uint32_t*)&a2; u0.w = *(uint32_t*)&a3;
                u1.x = *(uint32_t*)&a4; u1.y = *(uint32_t*)&a5; u1.z = *(uint32_t*)&a6; u1.w = *(uint32_t*)&a7;
            }
            *(uint4*)&PhQh[srow*SH + scol]     = u0;
            *(uint4*)&PhQh[srow*SH + scol + 8] = u1;
            // scatter into dense band: dd = j - (srow&31) + 31
            const int ql = srow & 31;
            #pragma unroll
            for (int i = 0; i < 16; i++)
                Bw[srow*SBW + scol + i - ql + 31] = __float2half_rn(p[i]);
        }
        if (kt < 15)
            pM = *(const uint4*)(g_mask8 + ((size_t)b*LL + q0 + srow)*LL + (k0 + 64) + scol);
        __syncthreads();

        // ---- GEMM2: oacc = csc*oacc + P@V + Band@TvwRing ----
        {
            float f00 = cscS[wr*32 + g],      f01 = cscS[wr*32 + 8 + g];
            float f10 = cscS[wr*32 + 16 + g], f11 = cscS[wr*32 + 24 + g];
            #pragma unroll
            for (int nt = 0; nt < 2; nt++) {
                oacc[0][nt][0] *= f00; oacc[0][nt][1] *= f00;
                oacc[0][nt][2] *= f01; oacc[0][nt][3] *= f01;
                oacc[1][nt][0] *= f10; oacc[1][nt][1] *= f10;
                oacc[1][nt][2] *= f11; oacc[1][nt][3] *= f11;
            }
            // P @ V (K=64)
            #pragma unroll
            for (int ksp = 0; ksp < 2; ksp++) {
                uint32_t ua[2][2][4];
                #pragma unroll
                for (int mt = 0; mt < 2; mt++)
                    #pragma unroll
                    for (int kk = 0; kk < 2; kk++) {
                        uint32_t ad = s2u(PhQh + (wr*32 + mt*16 + l15)*SH + (2*ksp+kk)*16 + lq16);
                        LDSM_X4(ua[mt][kk][0], ua[mt][kk][1], ua[mt][kk][2], ua[mt][kk][3], ad);
                    }
                #pragma unroll
                for (int nt = 0; nt < 2; nt++) {
                    uint32_t b0,b1,b2,b3;
                    uint32_t ad = s2u(Vt + (wc*16 + nt*8 + l7)*SH + ksp*32 + lq8);
                    LDSM_X4(b0,b1,b2,b3, ad);
                    #pragma unroll
                    for (int mt = 0; mt < 2; mt++) {
                        MMA_F16(oacc[mt][nt][0],oacc[mt][nt][1],oacc[mt][nt][2],oacc[mt][nt][3],
                                ua[mt][0][0],ua[mt][0][1],ua[mt][0][2],ua[mt][0][3], b0,b1);
                        MMA_F16(oacc[mt][nt][0],oacc[mt][nt][1],oacc[mt][nt][2],oacc[mt][nt][3],
                                ua[mt][1][0],ua[mt][1][1],ua[mt][1][2],ua[mt][1][3], b2,b3);
                    }
                }
            }
            // Band @ relV ring (K=96), ring base shifted per m-group
            const int sbase = (32 - 32*wr + kb) & 127;
            #pragma unroll
            for (int ksp = 0; ksp < 3; ksp++) {
                uint32_t ua[2][2][4];
                #pragma unroll
                for (int mt = 0; mt < 2; mt++)
                    #pragma unroll
                    for (int kk = 0; kk < 2; kk++) {
                        uint32_t ad = s2u(Bw + (wr*32 + mt*16 + l15)*SBW + (2*ksp+kk)*16 + lq16);
                        LDSM_X4(ua[mt][kk][0], ua[mt][kk][1], ua[mt][kk][2], ua[mt][kk][3], ad);
                    }
                const int colr = (sbase + ksp*32 + lq8) & 127;
                #pragma unroll
                for (int nt = 0; nt < 2; nt++) {
                    uint32_t b0,b1,b2,b3;
                    uint32_t ad = s2u(Tvwt + (wc*16 + nt*8 + l7)*SH2 + colr);
                    LDSM_X4(b0,b1,b2,b3, ad);
                    #pragma unroll
                    for (int mt = 0; mt < 2; mt++) {
                        MMA_F16(oacc[mt][nt][0],oacc[mt][nt][1],oacc[mt][nt][2],oacc[mt][nt][3],
                                ua[mt][0][0],ua[mt][0][1],ua[mt][0][2],ua[mt][0][3], b0,b1);
                        MMA_F16(oacc[mt][nt][0],oacc[mt][nt][1],oacc[mt][nt][2],oacc[mt][nt][3],
                                ua[mt][1][0],ua[mt][1][1],ua[mt][1][2],ua[mt][1][3], b2,b3);
                    }
                }
            }
        }
        __syncthreads();
    }

    // ---- epilogue ----
    #pragma unroll
    for (int mt = 0; mt < 2; mt++) {
        const int rowa = wr*32 + mt*16 + g;
        const int rowb = rowa + 8;
        const float la = 1.0f / lrowS[rowa];
        const float lb = 1.0f / lrowS[rowb];
        const size_t basea = (((size_t)((b*LL + q0 + rowa)*HH + h)) << 6);
        const size_t baseb = (((size_t)((b*LL + q0 + rowb)*HH + h)) << 6);
        #pragma unroll
        for (int nt = 0; nt < 2; nt++) {
            int c = wc*16 + nt*8 + 2*t;
            __half2 h0 = __floats2half2_rn(oacc[mt][nt][0]*la, oacc[mt][nt][1]*la);
            __half2 h1 = __floats2half2_rn(oacc[mt][nt][2]*lb, oacc[mt][nt][3]*lb);
            *(uint32_t*)(g_ctx + basea + c) = *(uint32_t*)&h0;
            *(uint32_t*)(g_ctx + baseb + c) = *(uint32_t*)&h1;
        }
    }
}

// ---------------------------------------------------------------------------
// Final FC, fp16 mma, 128x128 tiles, 512 threads, 2 CTAs/SM, reg prefetch.
// ---------------------------------------------------------------------------
__global__ __launch_bounds__(512, 2) void fc_kernel(
    const float* __restrict__ bfc, float* __restrict__ out)
{
    __shared__ __half Xs[128*SH];
    __shared__ __half Ws[128*SH];

    const int tid  = threadIdx.x;
    const int warp = tid >> 5, lane = tid & 31;
    const int g = lane >> 2, t = lane & 3;
    const int wr = warp >> 2, wc = warp & 3;
    const size_t r0 = (size_t)blockIdx.x * 128;
    const size_t n0 = (size_t)blockIdx.y * 128;

    const int rrA = tid >> 3,         ccA = (tid & 7) << 3;
    const int rrB = (tid + 512) >> 3, ccB = ((tid + 512) & 7) << 3;

    float oacc[2][4][4] = {};
    uint4 pX[2], pW[2];

    *(uint4*)&Xs[rrA*SH + ccA] = *(const uint4*)(g_ctx   + (r0 + rrA)*EMBN + ccA);
    *(uint4*)&Xs[rrB*SH + ccB] = *(const uint4*)(g_ctx   + (r0 + rrB)*EMBN + ccB);
    *(uint4*)&Ws[rrA*SH + ccA] = *(const uint4*)(g_Wfc_h + (n0 + rrA)*EMBN + ccA);
    *(uint4*)&Ws[rrB*SH + ccB] = *(const uint4*)(g_Wfc_h + (n0 + rrB)*EMBN + ccB);

    for (int e = 0; e < 16; e++) {
        __syncthreads();
        if (e < 15) {
            const int e0n = (e + 1) * 64;
            pX[0] = *(const uint4*)(g_ctx   + (r0 + rrA)*EMBN + e0n + ccA);
            pX[1] = *(const uint4*)(g_ctx   + (r0 + rrB)*EMBN + e0n + ccB);
            pW[0] = *(const uint4*)(g_Wfc_h + (n0 + rrA)*EMBN + e0n + ccA);
            pW[1] = *(const uint4*)(g_Wfc_h + (n0 + rrB)*EMBN + e0n + ccB);
        }
        #pragma unroll
        for (int ks = 0; ks < 4; ks++) {
            uint32_t a[2][4];
            #pragma unroll
            for (int mi = 0; mi < 2; mi++) {
                int ar = wr*32 + mi*16 + g;
                a[mi][0] = ldh2(&Xs[ ar   *SH + ks*16 + 2*t    ]);
                a[mi][1] = ldh2(&Xs[(ar+8)*SH + ks*16 + 2*t    ]);
                a[mi][2] = ldh2(&Xs[ ar   *SH + ks*16 + 2*t + 8]);
                a[mi][3] = ldh2(&Xs[(ar+8)*SH + ks*16 + 2*t + 8]);
            }
            #pragma unroll
            for (int nt = 0; nt < 4; nt++) {
                const __half* Bb = Ws + (wc*32 + nt*8 + g)*SH;
                uint32_t b0 = ldh2(Bb + ks*16 + 2*t);
                uint32_t b1 = ldh2(Bb + ks*16 + 2*t + 8);
                #pragma unroll
                for (int mi = 0; mi < 2; mi++)
                    MMA_F16(oacc[mi][nt][0], oacc[mi][nt][1], oacc[mi][nt][2], oacc[mi][nt][3],
                            a[mi][0], a[mi][1], a[mi][2], a[mi][3], b0, b1);
            }
        }
        __syncthreads();
        if (e < 15) {
            *(uint4*)&Xs[rrA*SH + ccA] = pX[0];
            *(uint4*)&Xs[rrB*SH + ccB] = pX[1];
            *(uint4*)&Ws[rrA*SH + ccA] = pW[0];
            *(uint4*)&Ws[rrB*SH + ccB] = pW[1];
        }
    }

    #pragma unroll
    for (int mi = 0; mi < 2; mi++) {
        size_t ra = r0 + wr*32 + mi*16 + g;
        #pragma unroll
        for (int nt = 0; nt < 4; nt++) {
            size_t c = n0 + wc*32 + nt*8 + 2*t;
            float bv0 = bfc[c], bv1 = bfc[c+1];
            *(float2*)(out + ra*EMBN + c) =
                make_float2(oacc[mi][nt][0] + bv0, oacc[mi][nt][1] + bv1);
            *(float2*)(out + (ra+8)*EMBN + c) =
                make_float2(oacc[mi][nt][2] + bv0, oacc[mi][nt][3] + bv1);
        }
    }
}

// ---------------------------------------------------------------------------
extern "C" void kernel_launch(void* const* d_in, const int* in_sizes, int n_in,
                              void* d_out, int out_size)
{
    const float* query = (const float*)d_in[0];
    const float* key_  = (const float*)d_in[1];
    const float* value = (const float*)d_in[2];
    const int*   mask  = (const int*)d_in[3];
    const float* Wq = (const float*)d_in[4];
    const float* bq = (const float*)d_in[5];
    const float* Wk = (const float*)d_in[6];
    const float* bk = (const float*)d_in[7];
    const float* Wv = (const float*)d_in[8];
    const float* bv = (const float*)d_in[9];
    const float* Wfc = (const float*)d_in[10];
    const float* bfc = (const float*)d_in[11];
    const float* relk = (const float*)d_in[12];
    const float* relv = (const float*)d_in[13];
    float* out = (float*)d_out;

    cudaFuncSetAttribute(attn_kernel, cudaFuncAttributeMaxDynamicSharedMemorySize, ATT_SMEM_BYTES);

    pre_kernel<<<dim3(1024, 4, 1), 256>>>(query, key_, value, Wq, bq, Wk, bk, Wv, bv,
                                          relk, relv, Wfc, mask);
    attn_kernel<<<dim3(16, 16, 4), 256, ATT_SMEM_BYTES>>>();
    fc_kernel<<<dim3(32, 8, 1), 512>>>(bfc, out);
}

// round 8
// speedup vs baseline: 1.3694x; 1.0373x over previous
#include <cuda_runtime.h>
#include <cuda_fp16.h>
#include <cstdint>
#include <cstddef>

#define BB   4
#define LL   1024
#define HH   16
#define DD   64
#define EMBN 1024
#define MAXREL 512
#define NREL (2*MAXREL + 1)

#define SH   72    // half stride, 64-wide tiles  (36 words == 4 mod 32)
#define SH2  136   // half stride, 128-wide tiles (68 words == 4 mod 32)
#define SQ   68    // float stride for SQK
#define SBW  104   // half stride, band buffer (52 words == 20 mod 32)

// Scratch (allocation-free rule: device globals)
__device__ __half g_qh [BB*LL*HH*DD];
__device__ __half g_kh [BB*LL*HH*DD];
__device__ __half g_vh [BB*LL*HH*DD];
__device__ __half g_ctx[BB*LL*HH*DD];
__device__ __half g_relk_h[NREL*DD];
__device__ __half g_relv_h[NREL*DD];
__device__ __half g_Wfc_h[EMBN*EMBN];
__device__ unsigned char g_mask8[BB*LL*LL];

// ---------------------------------------------------------------------------
#define MMA_F16(d0,d1,d2,d3,a0,a1,a2,a3,b0,b1)                               \
    asm volatile("mma.sync.aligned.m16n8k16.row.col.f32.f16.f16.f32 "        \
                 "{%0,%1,%2,%3}, {%4,%5,%6,%7}, {%8,%9}, {%0,%1,%2,%3};"     \
                 : "+f"(d0), "+f"(d1), "+f"(d2), "+f"(d3)                    \
                 : "r"(a0), "r"(a1), "r"(a2), "r"(a3), "r"(b0), "r"(b1))

#define LDSM_X4(r0,r1,r2,r3,addr)                                            \
    asm volatile("ldmatrix.sync.aligned.m8n8.x4.shared.b16 {%0,%1,%2,%3}, [%4];" \
                 : "=r"(r0), "=r"(r1), "=r"(r2), "=r"(r3) : "r"(addr))

__device__ __forceinline__ uint32_t ldh2(const __half* p) {
    return *(const uint32_t*)p;
}
__device__ __forceinline__ uint32_t s2u(const void* p) {
    return (uint32_t)__cvta_generic_to_shared(p);
}
__device__ __forceinline__ int clampdiff(int d) {
    return d < -MAXREL ? -MAXREL : (d > MAXREL ? MAXREL : d);
}
__device__ __forceinline__ uint2 f4_to_h4(float4 v) {
    __half2 h0 = __floats2half2_rn(v.x, v.y);
    __half2 h1 = __floats2half2_rn(v.z, v.w);
    uint2 r;
    r.x = *(uint32_t*)&h0;
    r.y = *(uint32_t*)&h1;
    return r;
}

// ---------------------------------------------------------------------------
// Pre: projections via fp16 mma (y = 0..2) + constant conversion (y = 3)
// ---------------------------------------------------------------------------
__global__ __launch_bounds__(256) void pre_kernel(
    const float* __restrict__ query, const float* __restrict__ key_, const float* __restrict__ value,
    const float* __restrict__ Wq, const float* __restrict__ bq,
    const float* __restrict__ Wk, const float* __restrict__ bk,
    const float* __restrict__ Wv, const float* __restrict__ bv,
    const float* __restrict__ relk, const float* __restrict__ relv,
    const float* __restrict__ Wfc,  const int* __restrict__ mask)
{
    const int tid = threadIdx.x;

    if (blockIdx.y == 3) {
        const int stride = 1024 * 256;
        const int base = blockIdx.x * 256 + tid;
        for (int i = base; i < NREL*DD; i += stride) {
            g_relk_h[i] = __float2half_rn(relk[i]);
            g_relv_h[i] = __float2half_rn(relv[i]);
        }
        for (int i = base; i < EMBN*EMBN; i += stride)
            g_Wfc_h[i] = __float2half_rn(Wfc[i]);
        for (int i = base; i < BB*LL*LL; i += stride)
            g_mask8[i] = (unsigned char)(mask[i] != 0);
        return;
    }

    __shared__ __half Xs[64*SH];
    __shared__ __half Ws[64*SH];
    __shared__ float bs[64];

    const float* X; const float* W; const float* bias; __half* out;
    if (blockIdx.y == 0)      { X = query; W = Wq; bias = bq; out = g_qh; }
    else if (blockIdx.y == 1) { X = key_;  W = Wk; bias = bk; out = g_kh; }
    else                      { X = value; W = Wv; bias = bv; out = g_vh; }

    const size_t r0 = (size_t)blockIdx.x * 64;
    const int warp = tid >> 5, lane = tid & 31;
    const int g = lane >> 2, t = lane & 3;
    const int wr = warp >> 2, wc = warp & 3;
    const int l7 = lane & 7, l15 = lane & 15;
    const int lq8 = (lane >> 3) << 3;
    const int lq16 = (lane >> 4) << 3;

    // stage X and W (fp32 -> fp16), 4 float4 each per thread
    {
        const int rr = tid >> 2, cb = (tid & 3) << 4;
        #pragma unroll
        for (int i = 0; i < 4; i++) {
            float4 v = *(const float4*)(X + (r0 + rr)*64 + cb + i*4);
            *(uint2*)&Xs[rr*SH + cb + i*4] = f4_to_h4(v);
            float4 w = *(const float4*)(W + (size_t)rr*64 + cb + i*4);
            *(uint2*)&Ws[rr*SH + cb + i*4] = f4_to_h4(w);
        }
    }
    if (tid < 64) bs[tid] = bias[tid];
    __syncthreads();

    // A fragments
    uint32_t qa[2][4][4];
    #pragma unroll
    for (int mt = 0; mt < 2; mt++)
        #pragma unroll
        for (int ks = 0; ks < 4; ks++) {
            uint32_t ad = s2u(Xs + (wr*32 + mt*16 + l15)*SH + ks*16 + lq16);
            LDSM_X4(qa[mt][ks][0], qa[mt][ks][1], qa[mt][ks][2], qa[mt][ks][3], ad);
        }

    #pragma unroll
    for (int nt = 0; nt < 2; nt++) {
        float c0[4] = {0,0,0,0}, c1[4] = {0,0,0,0};
        #pragma unroll
        for (int ksp = 0; ksp < 2; ksp++) {
            uint32_t b0,b1,b2,b3;
            uint32_t ad = s2u(Ws + (wc*16 + nt*8 + l7)*SH + ksp*32 + lq8);
            LDSM_X4(b0,b1,b2,b3, ad);
            MMA_F16(c0[0],c0[1],c0[2],c0[3], qa[0][2*ksp  ][0],qa[0][2*ksp  ][1],qa[0][2*ksp  ][2],qa[0][2*ksp  ][3], b0,b1);
            MMA_F16(c1[0],c1[1],c1[2],c1[3], qa[1][2*ksp  ][0],qa[1][2*ksp  ][1],qa[1][2*ksp  ][2],qa[1][2*ksp  ][3], b0,b1);
            MMA_F16(c0[0],c0[1],c0[2],c0[3], qa[0][2*ksp+1][0],qa[0][2*ksp+1][1],qa[0][2*ksp+1][2],qa[0][2*ksp+1][3], b2,b3);
            MMA_F16(c1[0],c1[1],c1[2],c1[3], qa[1][2*ksp+1][0],qa[1][2*ksp+1][1],qa[1][2*ksp+1][2],qa[1][2*ksp+1][3], b2,b3);
        }
        const int cb2 = wc*16 + nt*8 + 2*t;
        const float bv0 = bs[cb2], bv1 = bs[cb2 + 1];
        __half2 h00 = __floats2half2_rn(c0[0] + bv0, c0[1] + bv1);
        __half2 h01 = __floats2half2_rn(c0[2] + bv0, c0[3] + bv1);
        __half2 h10 = __floats2half2_rn(c1[0] + bv0, c1[1] + bv1);
        __half2 h11 = __floats2half2_rn(c1[2] + bv0, c1[3] + bv1);
        *(uint32_t*)(out + (r0 + wr*32      + g)*64 + cb2) = *(uint32_t*)&h00;
        *(uint32_t*)(out + (r0 + wr*32 +  8 + g)*64 + cb2) = *(uint32_t*)&h01;
        *(uint32_t*)(out + (r0 + wr*32 + 16 + g)*64 + cb2) = *(uint32_t*)&h10;
        *(uint32_t*)(out + (r0 + wr*32 + 24 + g)*64 + cb2) = *(uint32_t*)&h11;
    }
}

// ---------------------------------------------------------------------------
// Flash attention + relative bias. 256 threads = 8 warps (2 m-groups x 4 n).
// ldmatrix fragment loads, per-warp-group shifted band (K=96), full prefetch.
// ---------------------------------------------------------------------------
#define ATT_F_WORDS (64*SQ + 192)
#define ATT_H_WORDS (64*SH2 + 3*64*SH + 64*SH + 64*SH2 + 64*SBW)
#define ATT_SMEM_BYTES (ATT_F_WORDS*4 + ATT_H_WORDS*2)

__global__ __launch_bounds__(256, 2) void attn_kernel()
{
    extern __shared__ float smf[];
    float*  SQK   = smf;                      // 64 x SQ   fp32 QK scores
    float*  mrowS = SQK   + 64*SQ;            // 64
    float*  lrowS = mrowS + 64;               // 64
    float*  cscS  = lrowS + 64;               // 64
    __half* SrelH = (__half*)(cscS + 64);     // 64 x SH2  rel-score ring
    __half* Kh    = SrelH + 64*SH2;           // 64 x SH   [kpos][e]
    __half* Vt    = Kh    + 64*SH;            // 64 x SH   [d][kpos]
    __half* PhQh  = Vt    + 64*SH;            // 64 x SH   Q then probs [q][j]
    __half* Tkw   = PhQh  + 64*SH;            // 64 x SH   new rel_k block [j][e]
    __half* Tvwt  = Tkw   + 64*SH;            // 64 x SH2  rel_v ring [d][slot]
    __half* Bw    = Tvwt  + 64*SH2;           // 64 x SBW  dense band [q][dd]

    const int b  = blockIdx.z;
    const int h  = blockIdx.y;
    const int q0 = blockIdx.x * 64;
    const int tid  = threadIdx.x;
    const int warp = tid >> 5, lane = tid & 31;
    const int g = lane >> 2, t = lane & 3;
    const int wr = warp >> 2, wc = warp & 3;
    const int l7 = lane & 7, l15 = lane & 15;
    const int lq8 = (lane >> 3) << 3;
    const int lq16 = (lane >> 4) << 3;

    const int srow = tid >> 2;
    const int scol = (tid & 3) << 4;

    const int rrA = tid >> 3, ccA = (tid & 7) << 3;
    const int kp = tid & 63, dg = tid >> 6;

    if (tid < 64) { mrowS[tid] = -1e30f; lrowS[tid] = 0.0f; }

    // stage Q
    *(uint4*)&PhQh[ rrA      *SH + ccA] =
        *(const uint4*)(g_qh + (((size_t)((b*LL + q0 + rrA     )*HH + h)) << 6) + ccA);
    *(uint4*)&PhQh[(rrA + 32)*SH + ccA] =
        *(const uint4*)(g_qh + (((size_t)((b*LL + q0 + rrA + 32)*HH + h)) << 6) + ccA);

    uint4 pM = *(const uint4*)(g_mask8 + ((size_t)b*LL + q0 + srow)*LL + scol);
    __syncthreads();

    uint32_t qa[2][4][4];
    #pragma unroll
    for (int mt = 0; mt < 2; mt++)
        #pragma unroll
        for (int ks = 0; ks < 4; ks++) {
            uint32_t ad = s2u(PhQh + (wr*32 + mt*16 + l15)*SH + ks*16 + lq16);
            LDSM_X4(qa[mt][ks][0], qa[mt][ks][1], qa[mt][ks][2], qa[mt][ks][3], ad);
        }

    float oacc[2][2][4] = {};
    uint4 pK0, pK1, pV0, pV1, pRk0, pRk1;
    bool  havePf = false;

    for (int kt = 0; kt < 16; kt++) {
        const int k0 = kt * 64;
        const int d0 = k0 - q0;
        const int pb = ((kt + 1) & 1) << 6;
        const int kb = (kt & 1) << 6;

        // ---- clear dense band buffer ----
        {
            const uint4 z = make_uint4(0,0,0,0);
            #pragma unroll
            for (int i = 0; i < 4; i++) {
                int idx = tid + i*256;
                if (idx < 832) ((uint4*)Bw)[idx] = z;
            }
        }

        // ---- staging (prefetched except tile 0 / Tvwt) ----
        if (!havePf) {
            *(uint4*)&Kh[ rrA      *SH + ccA] =
                *(const uint4*)(g_kh + (((size_t)((b*LL + k0 + rrA     )*HH + h)) << 6) + ccA);
            *(uint4*)&Kh[(rrA + 32)*SH + ccA] =
                *(const uint4*)(g_kh + (((size_t)((b*LL + k0 + rrA + 32)*HH + h)) << 6) + ccA);
            pV0 = *(const uint4*)(g_vh + (((size_t)((b*LL + k0 + kp)*HH + h)) << 6) + dg*16);
            pV1 = *(const uint4*)(g_vh + (((size_t)((b*LL + k0 + kp)*HH + h)) << 6) + dg*16 + 8);
            int dfA = clampdiff(d0 + 0 + rrA - 63);
            int dfB = clampdiff(d0 + 0 + rrA + 32 - 63);
            *(uint4*)&Tkw[ rrA      *SH + ccA] = *(const uint4*)(g_relk_h + ((size_t)(dfA + MAXREL) << 6) + ccA);
            *(uint4*)&Tkw[(rrA + 32)*SH + ccA] = *(const uint4*)(g_relk_h + ((size_t)(dfB + MAXREL) << 6) + ccA);
        } else {
            *(uint4*)&Kh[ rrA      *SH + ccA] = pK0;
            *(uint4*)&Kh[(rrA + 32)*SH + ccA] = pK1;
            *(uint4*)&Tkw[ rrA      *SH + ccA] = pRk0;
            *(uint4*)&Tkw[(rrA + 32)*SH + ccA] = pRk1;
        }
        {
            const __half* v0 = (const __half*)&pV0;
            const __half* v1 = (const __half*)&pV1;
            #pragma unroll
            for (int j = 0; j < 8; j++) {
                Vt[(dg*16 + j    )*SH + kp] = v0[j];
                Vt[(dg*16 + j + 8)*SH + kp] = v1[j];
            }
        }
        // ---- Tvwt staging (direct, L2-resident) ----
        {
            const int jj0 = (kt == 0) ? 0 : 64;
            const int pbX = (kt == 0) ? 0 : pb;
            int df = clampdiff(d0 + jj0 + kp - 63);
            uint4 r0v = *(const uint4*)(g_relv_h + ((size_t)(df + MAXREL) << 6) + dg*16);
            uint4 r1v = *(const uint4*)(g_relv_h + ((size_t)(df + MAXREL) << 6) + dg*16 + 8);
            const __half* h0 = (const __half*)&r0v;
            const __half* h1 = (const __half*)&r1v;
            #pragma unroll
            for (int j = 0; j < 8; j++) {
                Tvwt[(dg*16 + j    )*SH2 + pbX + kp] = h0[j];
                Tvwt[(dg*16 + j + 8)*SH2 + pbX + kp] = h1[j];
            }
            if (kt == 0) {
                int df2 = clampdiff(d0 + 64 + kp - 63);
                uint4 r2v = *(const uint4*)(g_relv_h + ((size_t)(df2 + MAXREL) << 6) + dg*16);
                uint4 r3v = *(const uint4*)(g_relv_h + ((size_t)(df2 + MAXREL) << 6) + dg*16 + 8);
                const __half* h2 = (const __half*)&r2v;
                const __half* h3 = (const __half*)&r3v;
                #pragma unroll
                for (int j = 0; j < 8; j++) {
                    Tvwt[(dg*16 + j    )*SH2 + 64 + kp] = h2[j];
                    Tvwt[(dg*16 + j + 8)*SH2 + 64 + kp] = h3[j];
                }
            }
        }
        __syncthreads();

        // ---- prefetch everything for tile kt+1 ----
        if (kt < 15) {
            const int k0n = k0 + 64;
            const int d0n = k0n - q0;
            pK0 = *(const uint4*)(g_kh + (((size_t)((b*LL + k0n + rrA     )*HH + h)) << 6) + ccA);
            pK1 = *(const uint4*)(g_kh + (((size_t)((b*LL + k0n + rrA + 32)*HH + h)) << 6) + ccA);
            pV0 = *(const uint4*)(g_vh + (((size_t)((b*LL + k0n + kp)*HH + h)) << 6) + dg*16);
            pV1 = *(const uint4*)(g_vh + (((size_t)((b*LL + k0n + kp)*HH + h)) << 6) + dg*16 + 8);
            int dfA = clampdiff(d0n + 64 + rrA - 63);
            int dfB = clampdiff(d0n + 64 + rrA + 32 - 63);
            pRk0 = *(const uint4*)(g_relk_h + ((size_t)(dfA + MAXREL) << 6) + ccA);
            pRk1 = *(const uint4*)(g_relk_h + ((size_t)(dfB + MAXREL) << 6) + ccA);
            havePf = true;
        }

        // ---- GEMM1a: QK scores ----
        #pragma unroll
        for (int nt = 0; nt < 2; nt++) {
            float c0[4] = {0,0,0,0}, c1[4] = {0,0,0,0};
            #pragma unroll
            for (int ksp = 0; ksp < 2; ksp++) {
                uint32_t b0,b1,b2,b3;
                uint32_t ad = s2u(Kh + (wc*16 + nt*8 + l7)*SH + ksp*32 + lq8);
                LDSM_X4(b0,b1,b2,b3, ad);
                MMA_F16(c0[0],c0[1],c0[2],c0[3], qa[0][2*ksp  ][0],qa[0][2*ksp  ][1],qa[0][2*ksp  ][2],qa[0][2*ksp  ][3], b0,b1);
                MMA_F16(c1[0],c1[1],c1[2],c1[3], qa[1][2*ksp  ][0],qa[1][2*ksp  ][1],qa[1][2*ksp  ][2],qa[1][2*ksp  ][3], b0,b1);
                MMA_F16(c0[0],c0[1],c0[2],c0[3], qa[0][2*ksp+1][0],qa[0][2*ksp+1][1],qa[0][2*ksp+1][2],qa[0][2*ksp+1][3], b2,b3);
                MMA_F16(c1[0],c1[1],c1[2],c1[3], qa[1][2*ksp+1][0],qa[1][2*ksp+1][1],qa[1][2*ksp+1][2],qa[1][2*ksp+1][3], b2,b3);
            }
            const int colb = wc*16 + nt*8 + 2*t;
            *(float2*)&SQK[(wr*32      + g)*SQ + colb] = make_float2(c0[0],c0[1]);
            *(float2*)&SQK[(wr*32 +  8 + g)*SQ + colb] = make_float2(c0[2],c0[3]);
            *(float2*)&SQK[(wr*32 + 16 + g)*SQ + colb] = make_float2(c1[0],c1[1]);
            *(float2*)&SQK[(wr*32 + 24 + g)*SQ + colb] = make_float2(c1[2],c1[3]);
        }
        // ---- GEMM1b: rel scores -> SrelH ----
        {
            const int pbX = (kt == 0) ? 0 : pb;
            #pragma unroll
            for (int nt = 0; nt < 2; nt++) {
                float c0[4] = {0,0,0,0}, c1[4] = {0,0,0,0};
                #pragma unroll
                for (int ksp = 0; ksp < 2; ksp++) {
                    uint32_t b0,b1,b2,b3;
                    uint32_t ad = s2u(Tkw + (wc*16 + nt*8 + l7)*SH + ksp*32 + lq8);
                    LDSM_X4(b0,b1,b2,b3, ad);
                    MMA_F16(c0[0],c0[1],c0[2],c0[3], qa[0][2*ksp  ][0],qa[0][2*ksp  ][1],qa[0][2*ksp  ][2],qa[0][2*ksp  ][3], b0,b1);
                    MMA_F16(c1[0],c1[1],c1[2],c1[3], qa[1][2*ksp  ][0],qa[1][2*ksp  ][1],qa[1][2*ksp  ][2],qa[1][2*ksp  ][3], b0,b1);
                    MMA_F16(c0[0],c0[1],c0[2],c0[3], qa[0][2*ksp+1][0],qa[0][2*ksp+1][1],qa[0][2*ksp+1][2],qa[0][2*ksp+1][3], b2,b3);
                    MMA_F16(c1[0],c1[1],c1[2],c1[3], qa[1][2*ksp+1][0],qa[1][2*ksp+1][1],qa[1][2*ksp+1][2],qa[1][2*ksp+1][3], b2,b3);
                }
                const int colb = pbX + wc*16 + nt*8 + 2*t;
                __half2 h0 = __floats2half2_rn(c0[0],c0[1]);
                __half2 h1 = __floats2half2_rn(c0[2],c0[3]);
                __half2 h2 = __floats2half2_rn(c1[0],c1[1]);
                __half2 h3 = __floats2half2_rn(c1[2],c1[3]);
                *(uint32_t*)&SrelH[(wr*32      + g)*SH2 + colb] = *(uint32_t*)&h0;
                *(uint32_t*)&SrelH[(wr*32 +  8 + g)*SH2 + colb] = *(uint32_t*)&h1;
                *(uint32_t*)&SrelH[(wr*32 + 16 + g)*SH2 + colb] = *(uint32_t*)&h2;
                *(uint32_t*)&SrelH[(wr*32 + 24 + g)*SH2 + colb] = *(uint32_t*)&h3;
            }
        }
        // ---- tile 0 extra rel block ----
        if (kt == 0) {
            __syncthreads();
            {
                int dfA = clampdiff(d0 + 64 + rrA - 63);
                int dfB = clampdiff(d0 + 64 + rrA + 32 - 63);
                *(uint4*)&Tkw[ rrA      *SH + ccA] = *(const uint4*)(g_relk_h + ((size_t)(dfA + MAXREL) << 6) + ccA);
                *(uint4*)&Tkw[(rrA + 32)*SH + ccA] = *(const uint4*)(g_relk_h + ((size_t)(dfB + MAXREL) << 6) + ccA);
            }
            __syncthreads();
            #pragma unroll
            for (int nt = 0; nt < 2; nt++) {
                float c0[4] = {0,0,0,0}, c1[4] = {0,0,0,0};
                #pragma unroll
                for (int ksp = 0; ksp < 2; ksp++) {
                    uint32_t b0,b1,b2,b3;
                    uint32_t ad = s2u(Tkw + (wc*16 + nt*8 + l7)*SH + ksp*32 + lq8);
                    LDSM_X4(b0,b1,b2,b3, ad);
                    MMA_F16(c0[0],c0[1],c0[2],c0[3], qa[0][2*ksp  ][0],qa[0][2*ksp  ][1],qa[0][2*ksp  ][2],qa[0][2*ksp  ][3], b0,b1);
                    MMA_F16(c1[0],c1[1],c1[2],c1[3], qa[1][2*ksp  ][0],qa[1][2*ksp  ][1],qa[1][2*ksp  ][2],qa[1][2*ksp  ][3], b0,b1);
                    MMA_F16(c0[0],c0[1],c0[2],c0[3], qa[0][2*ksp+1][0],qa[0][2*ksp+1][1],qa[0][2*ksp+1][2],qa[0][2*ksp+1][3], b2,b3);
                    MMA_F16(c1[0],c1[1],c1[2],c1[3], qa[1][2*ksp+1][0],qa[1][2*ksp+1][1],qa[1][2*ksp+1][2],qa[1][2*ksp+1][3], b2,b3);
                }
                const int colb = 64 + wc*16 + nt*8 + 2*t;
                __half2 h0 = __floats2half2_rn(c0[0],c0[1]);
                __half2 h1 = __floats2half2_rn(c0[2],c0[3]);
                __half2 h2 = __floats2half2_rn(c1[0],c1[1]);
                __half2 h3 = __floats2half2_rn(c1[2],c1[3]);
                *(uint32_t*)&SrelH[(wr*32      + g)*SH2 + colb] = *(uint32_t*)&h0;
                *(uint32_t*)&SrelH[(wr*32 +  8 + g)*SH2 + colb] = *(uint32_t*)&h1;
                *(uint32_t*)&SrelH[(wr*32 + 16 + g)*SH2 + colb] = *(uint32_t*)&h2;
                *(uint32_t*)&SrelH[(wr*32 + 24 + g)*SH2 + colb] = *(uint32_t*)&h3;
            }
        }
        __syncthreads();

        // ---- softmax ----
        {
            float sv[16];
            *(float4*)&sv[0]  = *(const float4*)&SQK[srow*SQ + scol];
            *(float4*)&sv[4]  = *(const float4*)&SQK[srow*SQ + scol + 4];
            *(float4*)&sv[8]  = *(const float4*)&SQK[srow*SQ + scol + 8];
            *(float4*)&sv[12] = *(const float4*)&SQK[srow*SQ + scol + 12];
            uint32_t mw[4] = {pM.x, pM.y, pM.z, pM.w};
            #pragma unroll
            for (int i = 0; i < 16; i++) {
                uint32_t mb = (mw[i>>2] >> ((i & 3)*8)) & 0xffu;
                float rel = __half2float(SrelH[srow*SH2 + ((scol + i - srow + 63 + kb) & 127)]);
                float s = mb ? sv[i] : -1e20f;
                sv[i] = (s + rel) * 0.125f;
            }
            float rm = sv[0];
            #pragma unroll
            for (int i = 1; i < 16; i++) rm = fmaxf(rm, sv[i]);
            rm = fmaxf(rm, __shfl_xor_sync(0xffffffffu, rm, 1));
            rm = fmaxf(rm, __shfl_xor_sync(0xffffffffu, rm, 2));
            float mold = mrowS[srow];
            float mn = fmaxf(mold, rm);
            float csc = __expf(mold - mn);
            float p[16], ls = 0.f;
            #pragma unroll
            for (int i = 0; i < 16; i++) { p[i] = __expf(sv[i] - mn); ls += p[i]; }
            ls += __shfl_xor_sync(0xffffffffu, ls, 1);
            ls += __shfl_xor_sync(0xffffffffu, ls, 2);
            if ((tid & 3) == 0) {
                mrowS[srow] = mn;
                cscS[srow]  = csc;
                lrowS[srow] = lrowS[srow]*csc + ls;
            }
            uint4 u0, u1;
            {
                __half2 a0 = __floats2half2_rn(p[0],p[1]),  a1 = __floats2half2_rn(p[2],p[3]);
                __half2 a2 = __floats2half2_rn(p[4],p[5]),  a3 = __floats2half2_rn(p[6],p[7]);
                __half2 a4 = __floats2half2_rn(p[8],p[9]),  a5 = __floats2half2_rn(p[10],p[11]);
                __half2 a6 = __floats2half2_rn(p[12],p[13]),a7 = __floats2half2_rn(p[14],p[15]);
                u0.x = *(uint32_t*)&a0; u0.y = *(uint32_t*)&a1; u0.z = *(uint32_t*)&a2; u0.w = *(uint32_t*)&a3;
                u1.x = *(uint32_t*)&a4; u1.y = *(uint32_t*)&a5; u1.z = *(uint32_t*)&a6; u1.w = *(uint32_t*)&a7;
            }
            *(uint4*)&PhQh[srow*SH + scol]     = u0;
            *(uint4*)&PhQh[srow*SH + scol + 8] = u1;
            const int ql = srow & 31;
            #pragma unroll
            for (int i = 0; i < 16; i++)
                Bw[srow*SBW + scol + i - ql + 31] = __float2half_rn(p[i]);
        }
        if (kt < 15)
            pM = *(const uint4*)(g_mask8 + ((size_t)b*LL + q0 + srow)*LL + (k0 + 64) + scol);
        __syncthreads();

        // ---- GEMM2 ----
        {
            float f00 = cscS[wr*32 + g],      f01 = cscS[wr*32 + 8 + g];
            float f10 = cscS[wr*32 + 16 + g], f11 = cscS[wr*32 + 24 + g];
            #pragma unroll
            for (int nt = 0; nt < 2; nt++) {
                oacc[0][nt][0] *= f00; oacc[0][nt][1] *= f00;
                oacc[0][nt][2] *= f01; oacc[0][nt][3] *= f01;
                oacc[1][nt][0] *= f10; oacc[1][nt][1] *= f10;
                oacc[1][nt][2] *= f11; oacc[1][nt][3] *= f11;
            }
            #pragma unroll
            for (int ksp = 0; ksp < 2; ksp++) {
                uint32_t ua[2][2][4];
                #pragma unroll
                for (int mt = 0; mt < 2; mt++)
                    #pragma unroll
                    for (int kk = 0; kk < 2; kk++) {
                        uint32_t ad = s2u(PhQh + (wr*32 + mt*16 + l15)*SH + (2*ksp+kk)*16 + lq16);
                        LDSM_X4(ua[mt][kk][0], ua[mt][kk][1], ua[mt][kk][2], ua[mt][kk][3], ad);
                    }
                #pragma unroll
                for (int nt = 0; nt < 2; nt++) {
                    uint32_t b0,b1,b2,b3;
                    uint32_t ad = s2u(Vt + (wc*16 + nt*8 + l7)*SH + ksp*32 + lq8);
                    LDSM_X4(b0,b1,b2,b3, ad);
                    #pragma unroll
                    for (int mt = 0; mt < 2; mt++) {
                        MMA_F16(oacc[mt][nt][0],oacc[mt][nt][1],oacc[mt][nt][2],oacc[mt][nt][3],
                                ua[mt][0][0],ua[mt][0][1],ua[mt][0][2],ua[mt][0][3], b0,b1);
                        MMA_F16(oacc[mt][nt][0],oacc[mt][nt][1],oacc[mt][nt][2],oacc[mt][nt][3],
                                ua[mt][1][0],ua[mt][1][1],ua[mt][1][2],ua[mt][1][3], b2,b3);
                    }
                }
            }
            const int sbase = (32 - 32*wr + kb) & 127;
            #pragma unroll
            for (int ksp = 0; ksp < 3; ksp++) {
                uint32_t ua[2][2][4];
                #pragma unroll
                for (int mt = 0; mt < 2; mt++)
                    #pragma unroll
                    for (int kk = 0; kk < 2; kk++) {
                        uint32_t ad = s2u(Bw + (wr*32 + mt*16 + l15)*SBW + (2*ksp+kk)*16 + lq16);
                        LDSM_X4(ua[mt][kk][0], ua[mt][kk][1], ua[mt][kk][2], ua[mt][kk][3], ad);
                    }
                const int colr = (sbase + ksp*32 + lq8) & 127;
                #pragma unroll
                for (int nt = 0; nt < 2; nt++) {
                    uint32_t b0,b1,b2,b3;
                    uint32_t ad = s2u(Tvwt + (wc*16 + nt*8 + l7)*SH2 + colr);
                    LDSM_X4(b0,b1,b2,b3, ad);
                    #pragma unroll
                    for (int mt = 0; mt < 2; mt++) {
                        MMA_F16(oacc[mt][nt][0],oacc[mt][nt][1],oacc[mt][nt][2],oacc[mt][nt][3],
                                ua[mt][0][0],ua[mt][0][1],ua[mt][0][2],ua[mt][0][3], b0,b1);
                        MMA_F16(oacc[mt][nt][0],oacc[mt][nt][1],oacc[mt][nt][2],oacc[mt][nt][3],
                                ua[mt][1][0],ua[mt][1][1],ua[mt][1][2],ua[mt][1][3], b2,b3);
                    }
                }
            }
        }
        __syncthreads();
    }

    // ---- epilogue ----
    #pragma unroll
    for (int mt = 0; mt < 2; mt++) {
        const int rowa = wr*32 + mt*16 + g;
        const int rowb = rowa + 8;
        const float la = 1.0f / lrowS[rowa];
        const float lb = 1.0f / lrowS[rowb];
        const size_t basea = (((size_t)((b*LL + q0 + rowa)*HH + h)) << 6);
        const size_t baseb = (((size_t)((b*LL + q0 + rowb)*HH + h)) << 6);
        #pragma unroll
        for (int nt = 0; nt < 2; nt++) {
            int c = wc*16 + nt*8 + 2*t;
            __half2 h0 = __floats2half2_rn(oacc[mt][nt][0]*la, oacc[mt][nt][1]*la);
            __half2 h1 = __floats2half2_rn(oacc[mt][nt][2]*lb, oacc[mt][nt][3]*lb);
            *(uint32_t*)(g_ctx + basea + c) = *(uint32_t*)&h0;
            *(uint32_t*)(g_ctx + baseb + c) = *(uint32_t*)&h1;
        }
    }
}

// ---------------------------------------------------------------------------
// Final FC, fp16 mma, 128x128 tiles, 512 threads, 2 CTAs/SM, reg prefetch.
// ---------------------------------------------------------------------------
__global__ __launch_bounds__(512, 2) void fc_kernel(
    const float* __restrict__ bfc, float* __restrict__ out)
{
    __shared__ __half Xs[128*SH];
    __shared__ __half Ws[128*SH];

    const int tid  = threadIdx.x;
    const int warp = tid >> 5, lane = tid & 31;
    const int g = lane >> 2, t = lane & 3;
    const int wr = warp >> 2, wc = warp & 3;
    const size_t r0 = (size_t)blockIdx.x * 128;
    const size_t n0 = (size_t)blockIdx.y * 128;

    const int rrA = tid >> 3,         ccA = (tid & 7) << 3;
    const int rrB = (tid + 512) >> 3, ccB = ((tid + 512) & 7) << 3;

    float oacc[2][4][4] = {};
    uint4 pX[2], pW[2];

    *(uint4*)&Xs[rrA*SH + ccA] = *(const uint4*)(g_ctx   + (r0 + rrA)*EMBN + ccA);
    *(uint4*)&Xs[rrB*SH + ccB] = *(const uint4*)(g_ctx   + (r0 + rrB)*EMBN + ccB);
    *(uint4*)&Ws[rrA*SH + ccA] = *(const uint4*)(g_Wfc_h + (n0 + rrA)*EMBN + ccA);
    *(uint4*)&Ws[rrB*SH + ccB] = *(const uint4*)(g_Wfc_h + (n0 + rrB)*EMBN + ccB);

    for (int e = 0; e < 16; e++) {
        __syncthreads();
        if (e < 15) {
            const int e0n = (e + 1) * 64;
            pX[0] = *(const uint4*)(g_ctx   + (r0 + rrA)*EMBN + e0n + ccA);
            pX[1] = *(const uint4*)(g_ctx   + (r0 + rrB)*EMBN + e0n + ccB);
            pW[0] = *(const uint4*)(g_Wfc_h + (n0 + rrA)*EMBN + e0n + ccA);
            pW[1] = *(const uint4*)(g_Wfc_h + (n0 + rrB)*EMBN + e0n + ccB);
        }
        #pragma unroll
        for (int ks = 0; ks < 4; ks++) {
            uint32_t a[2][4];
            #pragma unroll
            for (int mi = 0; mi < 2; mi++) {
                int ar = wr*32 + mi*16 + g;
                a[mi][0] = ldh2(&Xs[ ar   *SH + ks*16 + 2*t    ]);
                a[mi][1] = ldh2(&Xs[(ar+8)*SH + ks*16 + 2*t    ]);
                a[mi][2] = ldh2(&Xs[ ar   *SH + ks*16 + 2*t + 8]);
                a[mi][3] = ldh2(&Xs[(ar+8)*SH + ks*16 + 2*t + 8]);
            }
            #pragma unroll
            for (int nt = 0; nt < 4; nt++) {
                const __half* Bb = Ws + (wc*32 + nt*8 + g)*SH;
                uint32_t b0 = ldh2(Bb + ks*16 + 2*t);
                uint32_t b1 = ldh2(Bb + ks*16 + 2*t + 8);
                #pragma unroll
                for (int mi = 0; mi < 2; mi++)
                    MMA_F16(oacc[mi][nt][0], oacc[mi][nt][1], oacc[mi][nt][2], oacc[mi][nt][3],
                            a[mi][0], a[mi][1], a[mi][2], a[mi][3], b0, b1);
            }
        }
        __syncthreads();
        if (e < 15) {
            *(uint4*)&Xs[rrA*SH + ccA] = pX[0];
            *(uint4*)&Xs[rrB*SH + ccB] = pX[1];
            *(uint4*)&Ws[rrA*SH + ccA] = pW[0];
            *(uint4*)&Ws[rrB*SH + ccB] = pW[1];
        }
    }

    #pragma unroll
    for (int mi = 0; mi < 2; mi++) {
        size_t ra = r0 + wr*32 + mi*16 + g;
        #pragma unroll
        for (int nt = 0; nt < 4; nt++) {
            size_t c = n0 + wc*32 + nt*8 + 2*t;
            float bv0 = bfc[c], bv1 = bfc[c+1];
            *(float2*)(out + ra*EMBN + c) =
                make_float2(oacc[mi][nt][0] + bv0, oacc[mi][nt][1] + bv1);
            *(float2*)(out + (ra+8)*EMBN + c) =
                make_float2(oacc[mi][nt][2] + bv0, oacc[mi][nt][3] + bv1);
        }
    }
}

// ---------------------------------------------------------------------------
extern "C" void kernel_launch(void* const* d_in, const int* in_sizes, int n_in,
                              void* d_out, int out_size)
{
    const float* query = (const float*)d_in[0];
    const float* key_  = (const float*)d_in[1];
    const float* value = (const float*)d_in[2];
    const int*   mask  = (const int*)d_in[3];
    const float* Wq = (const float*)d_in[4];
    const float* bq = (const float*)d_in[5];
    const float* Wk = (const float*)d_in[6];
    const float* bk = (const float*)d_in[7];
    const float* Wv = (const float*)d_in[8];
    const float* bv = (const float*)d_in[9];
    const float* Wfc = (const float*)d_in[10];
    const float* bfc = (const float*)d_in[11];
    const float* relk = (const float*)d_in[12];
    const float* relv = (const float*)d_in[13];
    float* out = (float*)d_out;

    cudaFuncSetAttribute(attn_kernel, cudaFuncAttributeMaxDynamicSharedMemorySize, ATT_SMEM_BYTES);

    pre_kernel<<<dim3(1024, 4, 1), 256>>>(query, key_, value, Wq, bq, Wk, bk, Wv, bv,
                                          relk, relv, Wfc, mask);
    attn_kernel<<<dim3(16, 16, 4), 256, ATT_SMEM_BYTES>>>();
    fc_kernel<<<dim3(32, 8, 1), 512>>>(bfc, out);
}

// round 9
// speedup vs baseline: 1.3710x; 1.0011x over previous
#include <cuda_runtime.h>
#include <cuda_fp16.h>
#include <cstdint>
#include <cstddef>

#define BB   4
#define LL   1024
#define HH   16
#define DD   64
#define EMBN 1024
#define MAXREL 512
#define NREL (2*MAXREL + 1)

#define SH   72    // half stride, 64-wide tiles  (36 words == 4 mod 32)
#define SH2  136   // half stride, 128-wide tiles (68 words == 4 mod 32)
#define SQ   68    // float stride for SQK
#define SBW  104   // half stride, band buffer (52 words == 20 mod 32)

// Scratch (allocation-free rule: device globals)
__device__ __half g_qh [BB*LL*HH*DD];
__device__ __half g_kh [BB*LL*HH*DD];
__device__ __half g_vh [BB*LL*HH*DD];
__device__ __half g_ctx[BB*LL*HH*DD];
__device__ __half g_relk_h[NREL*DD];
__device__ __half g_relv_h[NREL*DD];
__device__ __half g_Wfc_h[EMBN*EMBN];
__device__ unsigned char g_mask8[BB*LL*LL];

// ---------------------------------------------------------------------------
#define MMA_F16(d0,d1,d2,d3,a0,a1,a2,a3,b0,b1)                               \
    asm volatile("mma.sync.aligned.m16n8k16.row.col.f32.f16.f16.f32 "        \
                 "{%0,%1,%2,%3}, {%4,%5,%6,%7}, {%8,%9}, {%0,%1,%2,%3};"     \
                 : "+f"(d0), "+f"(d1), "+f"(d2), "+f"(d3)                    \
                 : "r"(a0), "r"(a1), "r"(a2), "r"(a3), "r"(b0), "r"(b1))

#define LDSM_X4(r0,r1,r2,r3,addr)                                            \
    asm volatile("ldmatrix.sync.aligned.m8n8.x4.shared.b16 {%0,%1,%2,%3}, [%4];" \
                 : "=r"(r0), "=r"(r1), "=r"(r2), "=r"(r3) : "r"(addr))

__device__ __forceinline__ uint32_t ldh2(const __half* p) {
    return *(const uint32_t*)p;
}
__device__ __forceinline__ uint32_t s2u(const void* p) {
    return (uint32_t)__cvta_generic_to_shared(p);
}
__device__ __forceinline__ int clampdiff(int d) {
    return d < -MAXREL ? -MAXREL : (d > MAXREL ? MAXREL : d);
}
__device__ __forceinline__ uint2 f4_to_h4(float4 v) {
    __half2 h0 = __floats2half2_rn(v.x, v.y);
    __half2 h1 = __floats2half2_rn(v.z, v.w);
    uint2 r;
    r.x = *(uint32_t*)&h0;
    r.y = *(uint32_t*)&h1;
    return r;
}

// ---------------------------------------------------------------------------
// Pre: projections via fp16 mma (y = 0..2) + constant conversion (y = 3)
// ---------------------------------------------------------------------------
__global__ __launch_bounds__(256) void pre_kernel(
    const float* __restrict__ query, const float* __restrict__ key_, const float* __restrict__ value,
    const float* __restrict__ Wq, const float* __restrict__ bq,
    const float* __restrict__ Wk, const float* __restrict__ bk,
    const float* __restrict__ Wv, const float* __restrict__ bv,
    const float* __restrict__ relk, const float* __restrict__ relv,
    const float* __restrict__ Wfc,  const int* __restrict__ mask)
{
    const int tid = threadIdx.x;

    if (blockIdx.y == 3) {
        const int stride = 1024 * 256;
        const int base = blockIdx.x * 256 + tid;
        for (int i = base; i < NREL*DD; i += stride) {
            g_relk_h[i] = __float2half_rn(relk[i]);
            g_relv_h[i] = __float2half_rn(relv[i]);
        }
        for (int i = base; i < EMBN*EMBN; i += stride)
            g_Wfc_h[i] = __float2half_rn(Wfc[i]);
        for (int i = base; i < BB*LL*LL; i += stride)
            g_mask8[i] = (unsigned char)(mask[i] != 0);
        return;
    }

    __shared__ __half Xs[64*SH];
    __shared__ __half Ws[64*SH];
    __shared__ float bs[64];

    const float* X; const float* W; const float* bias; __half* out;
    if (blockIdx.y == 0)      { X = query; W = Wq; bias = bq; out = g_qh; }
    else if (blockIdx.y == 1) { X = key_;  W = Wk; bias = bk; out = g_kh; }
    else                      { X = value; W = Wv; bias = bv; out = g_vh; }

    const size_t r0 = (size_t)blockIdx.x * 64;
    const int warp = tid >> 5, lane = tid & 31;
    const int g = lane >> 2, t = lane & 3;
    const int wr = warp >> 2, wc = warp & 3;
    const int l7 = lane & 7, l15 = lane & 15;
    const int lq8 = (lane >> 3) << 3;
    const int lq16 = (lane >> 4) << 3;

    // stage X and W (fp32 -> fp16), 4 float4 each per thread
    {
        const int rr = tid >> 2, cb = (tid & 3) << 4;
        #pragma unroll
        for (int i = 0; i < 4; i++) {
            float4 v = *(const float4*)(X + (r0 + rr)*64 + cb + i*4);
            *(uint2*)&Xs[rr*SH + cb + i*4] = f4_to_h4(v);
            float4 w = *(const float4*)(W + (size_t)rr*64 + cb + i*4);
            *(uint2*)&Ws[rr*SH + cb + i*4] = f4_to_h4(w);
        }
    }
    if (tid < 64) bs[tid] = bias[tid];
    __syncthreads();

    // A fragments
    uint32_t qa[2][4][4];
    #pragma unroll
    for (int mt = 0; mt < 2; mt++)
        #pragma unroll
        for (int ks = 0; ks < 4; ks++) {
            uint32_t ad = s2u(Xs + (wr*32 + mt*16 + l15)*SH + ks*16 + lq16);
            LDSM_X4(qa[mt][ks][0], qa[mt][ks][1], qa[mt][ks][2], qa[mt][ks][3], ad);
        }

    #pragma unroll
    for (int nt = 0; nt < 2; nt++) {
        float c0[4] = {0,0,0,0}, c1[4] = {0,0,0,0};
        #pragma unroll
        for (int ksp = 0; ksp < 2; ksp++) {
            uint32_t b0,b1,b2,b3;
            uint32_t ad = s2u(Ws + (wc*16 + nt*8 + l7)*SH + ksp*32 + lq8);
            LDSM_X4(b0,b1,b2,b3, ad);
            MMA_F16(c0[0],c0[1],c0[2],c0[3], qa[0][2*ksp  ][0],qa[0][2*ksp  ][1],qa[0][2*ksp  ][2],qa[0][2*ksp  ][3], b0,b1);
            MMA_F16(c1[0],c1[1],c1[2],c1[3], qa[1][2*ksp  ][0],qa[1][2*ksp  ][1],qa[1][2*ksp  ][2],qa[1][2*ksp  ][3], b0,b1);
            MMA_F16(c0[0],c0[1],c0[2],c0[3], qa[0][2*ksp+1][0],qa[0][2*ksp+1][1],qa[0][2*ksp+1][2],qa[0][2*ksp+1][3], b2,b3);
            MMA_F16(c1[0],c1[1],c1[2],c1[3], qa[1][2*ksp+1][0],qa[1][2*ksp+1][1],qa[1][2*ksp+1][2],qa[1][2*ksp+1][3], b2,b3);
        }
        const int cb2 = wc*16 + nt*8 + 2*t;
        const float bv0 = bs[cb2], bv1 = bs[cb2 + 1];
        __half2 h00 = __floats2half2_rn(c0[0] + bv0, c0[1] + bv1);
        __half2 h01 = __floats2half2_rn(c0[2] + bv0, c0[3] + bv1);
        __half2 h10 = __floats2half2_rn(c1[0] + bv0, c1[1] + bv1);
        __half2 h11 = __floats2half2_rn(c1[2] + bv0, c1[3] + bv1);
        *(uint32_t*)(out + (r0 + wr*32      + g)*64 + cb2) = *(uint32_t*)&h00;
        *(uint32_t*)(out + (r0 + wr*32 +  8 + g)*64 + cb2) = *(uint32_t*)&h01;
        *(uint32_t*)(out + (r0 + wr*32 + 16 + g)*64 + cb2) = *(uint32_t*)&h10;
        *(uint32_t*)(out + (r0 + wr*32 + 24 + g)*64 + cb2) = *(uint32_t*)&h11;
    }
}

// ---------------------------------------------------------------------------
// Flash attention + relative bias. 256 threads = 8 warps (2 m-groups x 4 n).
// ldmatrix fragment loads, per-warp-group shifted band (K=96), full prefetch.
// ---------------------------------------------------------------------------
#define ATT_F_WORDS (64*SQ + 192)
#define ATT_H_WORDS (64*SH2 + 3*64*SH + 64*SH + 64*SH2 + 64*SBW)
#define ATT_SMEM_BYTES (ATT_F_WORDS*4 + ATT_H_WORDS*2)

__global__ __launch_bounds__(256, 2) void attn_kernel()
{
    extern __shared__ float smf[];
    float*  SQK   = smf;                      // 64 x SQ   fp32 QK scores
    float*  mrowS = SQK   + 64*SQ;            // 64
    float*  lrowS = mrowS + 64;               // 64
    float*  cscS  = lrowS + 64;               // 64
    __half* SrelH = (__half*)(cscS + 64);     // 64 x SH2  rel-score ring
    __half* Kh    = SrelH + 64*SH2;           // 64 x SH   [kpos][e]
    __half* Vt    = Kh    + 64*SH;            // 64 x SH   [d][kpos]
    __half* PhQh  = Vt    + 64*SH;            // 64 x SH   Q then probs [q][j]
    __half* Tkw   = PhQh  + 64*SH;            // 64 x SH   new rel_k block [j][e]
    __half* Tvwt  = Tkw   + 64*SH;            // 64 x SH2  rel_v ring [d][slot]
    __half* Bw    = Tvwt  + 64*SH2;           // 64 x SBW  dense band [q][dd]

    const int b  = blockIdx.z;
    const int h  = blockIdx.y;
    const int q0 = blockIdx.x * 64;
    const int tid  = threadIdx.x;
    const int warp = tid >> 5, lane = tid & 31;
    const int g = lane >> 2, t = lane & 3;
    const int wr = warp >> 2, wc = warp & 3;
    const int l7 = lane & 7, l15 = lane & 15;
    const int lq8 = (lane >> 3) << 3;
    const int lq16 = (lane >> 4) << 3;

    const int srow = tid >> 2;
    const int scol = (tid & 3) << 4;

    const int rrA = tid >> 3, ccA = (tid & 7) << 3;
    const int kp = tid & 63, dg = tid >> 6;

    if (tid < 64) { mrowS[tid] = -1e30f; lrowS[tid] = 0.0f; }

    // stage Q
    *(uint4*)&PhQh[ rrA      *SH + ccA] =
        *(const uint4*)(g_qh + (((size_t)((b*LL + q0 + rrA     )*HH + h)) << 6) + ccA);
    *(uint4*)&PhQh[(rrA + 32)*SH + ccA] =
        *(const uint4*)(g_qh + (((size_t)((b*LL + q0 + rrA + 32)*HH + h)) << 6) + ccA);

    uint4 pM = *(const uint4*)(g_mask8 + ((size_t)b*LL + q0 + srow)*LL + scol);
    __syncthreads();

    uint32_t qa[2][4][4];
    #pragma unroll
    for (int mt = 0; mt < 2; mt++)
        #pragma unroll
        for (int ks = 0; ks < 4; ks++) {
            uint32_t ad = s2u(PhQh + (wr*32 + mt*16 + l15)*SH + ks*16 + lq16);
            LDSM_X4(qa[mt][ks][0], qa[mt][ks][1], qa[mt][ks][2], qa[mt][ks][3], ad);
        }

    float oacc[2][2][4] = {};
    uint4 pK0, pK1, pV0, pV1, pRk0, pRk1;
    bool  havePf = false;

    for (int kt = 0; kt < 16; kt++) {
        const int k0 = kt * 64;
        const int d0 = k0 - q0;
        const int pb = ((kt + 1) & 1) << 6;
        const int kb = (kt & 1) << 6;

        // ---- clear dense band buffer ----
        {
            const uint4 z = make_uint4(0,0,0,0);
            #pragma unroll
            for (int i = 0; i < 4; i++) {
                int idx = tid + i*256;
                if (idx < 832) ((uint4*)Bw)[idx] = z;
            }
        }

        // ---- staging (prefetched except tile 0 / Tvwt) ----
        if (!havePf) {
            *(uint4*)&Kh[ rrA      *SH + ccA] =
                *(const uint4*)(g_kh + (((size_t)((b*LL + k0 + rrA     )*HH + h)) << 6) + ccA);
            *(uint4*)&Kh[(rrA + 32)*SH + ccA] =
                *(const uint4*)(g_kh + (((size_t)((b*LL + k0 + rrA + 32)*HH + h)) << 6) + ccA);
            pV0 = *(const uint4*)(g_vh + (((size_t)((b*LL + k0 + kp)*HH + h)) << 6) + dg*16);
            pV1 = *(const uint4*)(g_vh + (((size_t)((b*LL + k0 + kp)*HH + h)) << 6) + dg*16 + 8);
            int dfA = clampdiff(d0 + 0 + rrA - 63);
            int dfB = clampdiff(d0 + 0 + rrA + 32 - 63);
            *(uint4*)&Tkw[ rrA      *SH + ccA] = *(const uint4*)(g_relk_h + ((size_t)(dfA + MAXREL) << 6) + ccA);
            *(uint4*)&Tkw[(rrA + 32)*SH + ccA] = *(const uint4*)(g_relk_h + ((size_t)(dfB + MAXREL) << 6) + ccA);
        } else {
            *(uint4*)&Kh[ rrA      *SH + ccA] = pK0;
            *(uint4*)&Kh[(rrA + 32)*SH + ccA] = pK1;
            *(uint4*)&Tkw[ rrA      *SH + ccA] = pRk0;
            *(uint4*)&Tkw[(rrA + 32)*SH + ccA] = pRk1;
        }
        {
            const __half* v0 = (const __half*)&pV0;
            const __half* v1 = (const __half*)&pV1;
            #pragma unroll
            for (int j = 0; j < 8; j++) {
                Vt[(dg*16 + j    )*SH + kp] = v0[j];
                Vt[(dg*16 + j + 8)*SH + kp] = v1[j];
            }
        }
        // ---- Tvwt staging (direct, L2-resident) ----
        {
            const int jj0 = (kt == 0) ? 0 : 64;
            const int pbX = (kt == 0) ? 0 : pb;
            int df = clampdiff(d0 + jj0 + kp - 63);
            uint4 r0v = *(const uint4*)(g_relv_h + ((size_t)(df + MAXREL) << 6) + dg*16);
            uint4 r1v = *(const uint4*)(g_relv_h + ((size_t)(df + MAXREL) << 6) + dg*16 + 8);
            const __half* h0 = (const __half*)&r0v;
            const __half* h1 = (const __half*)&r1v;
            #pragma unroll
            for (int j = 0; j < 8; j++) {
                Tvwt[(dg*16 + j    )*SH2 + pbX + kp] = h0[j];
                Tvwt[(dg*16 + j + 8)*SH2 + pbX + kp] = h1[j];
            }
            if (kt == 0) {
                int df2 = clampdiff(d0 + 64 + kp - 63);
                uint4 r2v = *(const uint4*)(g_relv_h + ((size_t)(df2 + MAXREL) << 6) + dg*16);
                uint4 r3v = *(const uint4*)(g_relv_h + ((size_t)(df2 + MAXREL) << 6) + dg*16 + 8);
                const __half* h2 = (const __half*)&r2v;
                const __half* h3 = (const __half*)&r3v;
                #pragma unroll
                for (int j = 0; j < 8; j++) {
                    Tvwt[(dg*16 + j    )*SH2 + 64 + kp] = h2[j];
                    Tvwt[(dg*16 + j + 8)*SH2 + 64 + kp] = h3[j];
                }
            }
        }
        __syncthreads();

        // ---- prefetch everything for tile kt+1 ----
        if (kt < 15) {
            const int k0n = k0 + 64;
            const int d0n = k0n - q0;
            pK0 = *(const uint4*)(g_kh + (((size_t)((b*LL + k0n + rrA     )*HH + h)) << 6) + ccA);
            pK1 = *(const uint4*)(g_kh + (((size_t)((b*LL + k0n + rrA + 32)*HH + h)) << 6) + ccA);
            pV0 = *(const uint4*)(g_vh + (((size_t)((b*LL + k0n + kp)*HH + h)) << 6) + dg*16);
            pV1 = *(const uint4*)(g_vh + (((size_t)((b*LL + k0n + kp)*HH + h)) << 6) + dg*16 + 8);
            int dfA = clampdiff(d0n + 64 + rrA - 63);
            int dfB = clampdiff(d0n + 64 + rrA + 32 - 63);
            pRk0 = *(const uint4*)(g_relk_h + ((size_t)(dfA + MAXREL) << 6) + ccA);
            pRk1 = *(const uint4*)(g_relk_h + ((size_t)(dfB + MAXREL) << 6) + ccA);
            havePf = true;
        }

        // ---- GEMM1a: QK scores ----
        #pragma unroll
        for (int nt = 0; nt < 2; nt++) {
            float c0[4] = {0,0,0,0}, c1[4] = {0,0,0,0};
            #pragma unroll
            for (int ksp = 0; ksp < 2; ksp++) {
                uint32_t b0,b1,b2,b3;
                uint32_t ad = s2u(Kh + (wc*16 + nt*8 + l7)*SH + ksp*32 + lq8);
                LDSM_X4(b0,b1,b2,b3, ad);
                MMA_F16(c0[0],c0[1],c0[2],c0[3], qa[0][2*ksp  ][0],qa[0][2*ksp  ][1],qa[0][2*ksp  ][2],qa[0][2*ksp  ][3], b0,b1);
                MMA_F16(c1[0],c1[1],c1[2],c1[3], qa[1][2*ksp  ][0],qa[1][2*ksp  ][1],qa[1][2*ksp  ][2],qa[1][2*ksp  ][3], b0,b1);
                MMA_F16(c0[0],c0[1],c0[2],c0[3], qa[0][2*ksp+1][0],qa[0][2*ksp+1][1],qa[0][2*ksp+1][2],qa[0][2*ksp+1][3], b2,b3);
                MMA_F16(c1[0],c1[1],c1[2],c1[3], qa[1][2*ksp+1][0],qa[1][2*ksp+1][1],qa[1][2*ksp+1][2],qa[1][2*ksp+1][3], b2,b3);
            }
            const int colb = wc*16 + nt*8 + 2*t;
            *(float2*)&SQK[(wr*32      + g)*SQ + colb] = make_float2(c0[0],c0[1]);
            *(float2*)&SQK[(wr*32 +  8 + g)*SQ + colb] = make_float2(c0[2],c0[3]);
            *(float2*)&SQK[(wr*32 + 16 + g)*SQ + colb] = make_float2(c1[0],c1[1]);
            *(float2*)&SQK[(wr*32 + 24 + g)*SQ + colb] = make_float2(c1[2],c1[3]);
        }
        // ---- GEMM1b: rel scores -> SrelH ----
        {
            const int pbX = (kt == 0) ? 0 : pb;
            #pragma unroll
            for (int nt = 0; nt < 2; nt++) {
                float c0[4] = {0,0,0,0}, c1[4] = {0,0,0,0};
                #pragma unroll
                for (int ksp = 0; ksp < 2; ksp++) {
                    uint32_t b0,b1,b2,b3;
                    uint32_t ad = s2u(Tkw + (wc*16 + nt*8 + l7)*SH + ksp*32 + lq8);
                    LDSM_X4(b0,b1,b2,b3, ad);
                    MMA_F16(c0[0],c0[1],c0[2],c0[3], qa[0][2*ksp  ][0],qa[0][2*ksp  ][1],qa[0][2*ksp  ][2],qa[0][2*ksp  ][3], b0,b1);
                    MMA_F16(c1[0],c1[1],c1[2],c1[3], qa[1][2*ksp  ][0],qa[1][2*ksp  ][1],qa[1][2*ksp  ][2],qa[1][2*ksp  ][3], b0,b1);
                    MMA_F16(c0[0],c0[1],c0[2],c0[3], qa[0][2*ksp+1][0],qa[0][2*ksp+1][1],qa[0][2*ksp+1][2],qa[0][2*ksp+1][3], b2,b3);
                    MMA_F16(c1[0],c1[1],c1[2],c1[3], qa[1][2*ksp+1][0],qa[1][2*ksp+1][1],qa[1][2*ksp+1][2],qa[1][2*ksp+1][3], b2,b3);
                }
                const int colb = pbX + wc*16 + nt*8 + 2*t;
                __half2 h0 = __floats2half2_rn(c0[0],c0[1]);
                __half2 h1 = __floats2half2_rn(c0[2],c0[3]);
                __half2 h2 = __floats2half2_rn(c1[0],c1[1]);
                __half2 h3 = __floats2half2_rn(c1[2],c1[3]);
                *(uint32_t*)&SrelH[(wr*32      + g)*SH2 + colb] = *(uint32_t*)&h0;
                *(uint32_t*)&SrelH[(wr*32 +  8 + g)*SH2 + colb] = *(uint32_t*)&h1;
                *(uint32_t*)&SrelH[(wr*32 + 16 + g)*SH2 + colb] = *(uint32_t*)&h2;
                *(uint32_t*)&SrelH[(wr*32 + 24 + g)*SH2 + colb] = *(uint32_t*)&h3;
            }
        }
        // ---- tile 0 extra rel block ----
        if (kt == 0) {
            __syncthreads();
            {
                int dfA = clampdiff(d0 + 64 + rrA - 63);
                int dfB = clampdiff(d0 + 64 + rrA + 32 - 63);
                *(uint4*)&Tkw[ rrA      *SH + ccA] = *(const uint4*)(g_relk_h + ((size_t)(dfA + MAXREL) << 6) + ccA);
                *(uint4*)&Tkw[(rrA + 32)*SH + ccA] = *(const uint4*)(g_relk_h + ((size_t)(dfB + MAXREL) << 6) + ccA);
            }
            __syncthreads();
            #pragma unroll
            for (int nt = 0; nt < 2; nt++) {
                float c0[4] = {0,0,0,0}, c1[4] = {0,0,0,0};
                #pragma unroll
                for (int ksp = 0; ksp < 2; ksp++) {
                    uint32_t b0,b1,b2,b3;
                    uint32_t ad = s2u(Tkw + (wc*16 + nt*8 + l7)*SH + ksp*32 + lq8);
                    LDSM_X4(b0,b1,b2,b3, ad);
                    MMA_F16(c0[0],c0[1],c0[2],c0[3], qa[0][2*ksp  ][0],qa[0][2*ksp  ][1],qa[0][2*ksp  ][2],qa[0][2*ksp  ][3], b0,b1);
                    MMA_F16(c1[0],c1[1],c1[2],c1[3], qa[1][2*ksp  ][0],qa[1][2*ksp  ][1],qa[1][2*ksp  ][2],qa[1][2*ksp  ][3], b0,b1);
                    MMA_F16(c0[0],c0[1],c0[2],c0[3], qa[0][2*ksp+1][0],qa[0][2*ksp+1][1],qa[0][2*ksp+1][2],qa[0][2*ksp+1][3], b2,b3);
                    MMA_F16(c1[0],c1[1],c1[2],c1[3], qa[1][2*ksp+1][0],qa[1][2*ksp+1][1],qa[1][2*ksp+1][2],qa[1][2*ksp+1][3], b2,b3);
                }
                const int colb = 64 + wc*16 + nt*8 + 2*t;
                __half2 h0 = __floats2half2_rn(c0[0],c0[1]);
                __half2 h1 = __floats2half2_rn(c0[2],c0[3]);
                __half2 h2 = __floats2half2_rn(c1[0],c1[1]);
                __half2 h3 = __floats2half2_rn(c1[2],c1[3]);
                *(uint32_t*)&SrelH[(wr*32      + g)*SH2 + colb] = *(uint32_t*)&h0;
                *(uint32_t*)&SrelH[(wr*32 +  8 + g)*SH2 + colb] = *(uint32_t*)&h1;
                *(uint32_t*)&SrelH[(wr*32 + 16 + g)*SH2 + colb] = *(uint32_t*)&h2;
                *(uint32_t*)&SrelH[(wr*32 + 24 + g)*SH2 + colb] = *(uint32_t*)&h3;
            }
        }
        __syncthreads();

        // ---- softmax ----
        {
            float sv[16];
            *(float4*)&sv[0]  = *(const float4*)&SQK[srow*SQ + scol];
            *(float4*)&sv[4]  = *(const float4*)&SQK[srow*SQ + scol + 4];
            *(float4*)&sv[8]  = *(const float4*)&SQK[srow*SQ + scol + 8];
            *(float4*)&sv[12] = *(const float4*)&SQK[srow*SQ + scol + 12];
            uint32_t mw[4] = {pM.x, pM.y, pM.z, pM.w};
            #pragma unroll
            for (int i = 0; i < 16; i++) {
                uint32_t mb = (mw[i>>2] >> ((i & 3)*8)) & 0xffu;
                float rel = __half2float(SrelH[srow*SH2 + ((scol + i - srow + 63 + kb) & 127)]);
                float s = mb ? sv[i] : -1e20f;
                sv[i] = (s + rel) * 0.125f;
            }
            float rm = sv[0];
            #pragma unroll
            for (int i = 1; i < 16; i++) rm = fmaxf(rm, sv[i]);
            rm = fmaxf(rm, __shfl_xor_sync(0xffffffffu, rm, 1));
            rm = fmaxf(rm, __shfl_xor_sync(0xffffffffu, rm, 2));
            float mold = mrowS[srow];
            float mn = fmaxf(mold, rm);
            float csc = __expf(mold - mn);
            float p[16], ls = 0.f;
            #pragma unroll
            for (int i = 0; i < 16; i++) { p[i] = __expf(sv[i] - mn); ls += p[i]; }
            ls += __shfl_xor_sync(0xffffffffu, ls, 1);
            ls += __shfl_xor_sync(0xffffffffu, ls, 2);
            if ((tid & 3) == 0) {
                mrowS[srow] = mn;
                cscS[srow]  = csc;
                lrowS[srow] = lrowS[srow]*csc + ls;
            }
            uint4 u0, u1;
            {
                __half2 a0 = __floats2half2_rn(p[0],p[1]),  a1 = __floats2half2_rn(p[2],p[3]);
                __half2 a2 = __floats2half2_rn(p[4],p[5]),  a3 = __floats2half2_rn(p[6],p[7]);
                __half2 a4 = __floats2half2_rn(p[8],p[9]),  a5 = __floats2half2_rn(p[10],p[11]);
                __half2 a6 = __floats2half2_rn(p[12],p[13]),a7 = __floats2half2_rn(p[14],p[15]);
                u0.x = *(uint32_t*)&a0; u0.y = *(uint32_t*)&a1; u0.z = *(uint32_t*)&a2; u0.w = *(uint32_t*)&a3;
                u1.x = *(uint32_t*)&a4; u1.y = *(uint32_t*)&a5; u1.z = *(uint32_t*)&a6; u1.w = *(uint32_t*)&a7;
            }
            *(uint4*)&PhQh[srow*SH + scol]     = u0;
            *(uint4*)&PhQh[srow*SH + scol + 8] = u1;
            const int ql = srow & 31;
            #pragma unroll
            for (int i = 0; i < 16; i++)
                Bw[srow*SBW + scol + i - ql + 31] = __float2half_rn(p[i]);
        }
        if (kt < 15)
            pM = *(const uint4*)(g_mask8 + ((size_t)b*LL + q0 + srow)*LL + (k0 + 64) + scol);
        __syncthreads();

        // ---- GEMM2 ----
        {
            float f00 = cscS[wr*32 + g],      f01 = cscS[wr*32 + 8 + g];
            float f10 = cscS[wr*32 + 16 + g], f11 = cscS[wr*32 + 24 + g];
            #pragma unroll
            for (int nt = 0; nt < 2; nt++) {
                oacc[0][nt][0] *= f00; oacc[0][nt][1] *= f00;
                oacc[0][nt][2] *= f01; oacc[0][nt][3] *= f01;
                oacc[1][nt][0] *= f10; oacc[1][nt][1] *= f10;
                oacc[1][nt][2] *= f11; oacc[1][nt][3] *= f11;
            }
            #pragma unroll
            for (int ksp = 0; ksp < 2; ksp++) {
                uint32_t ua[2][2][4];
                #pragma unroll
                for (int mt = 0; mt < 2; mt++)
                    #pragma unroll
                    for (int kk = 0; kk < 2; kk++) {
                        uint32_t ad = s2u(PhQh + (wr*32 + mt*16 + l15)*SH + (2*ksp+kk)*16 + lq16);
                        LDSM_X4(ua[mt][kk][0], ua[mt][kk][1], ua[mt][kk][2], ua[mt][kk][3], ad);
                    }
                #pragma unroll
                for (int nt = 0; nt < 2; nt++) {
                    uint32_t b0,b1,b2,b3;
                    uint32_t ad = s2u(Vt + (wc*16 + nt*8 + l7)*SH + ksp*32 + lq8);
                    LDSM_X4(b0,b1,b2,b3, ad);
                    #pragma unroll
                    for (int mt = 0; mt < 2; mt++) {
                        MMA_F16(oacc[mt][nt][0],oacc[mt][nt][1],oacc[mt][nt][2],oacc[mt][nt][3],
                                ua[mt][0][0],ua[mt][0][1],ua[mt][0][2],ua[mt][0][3], b0,b1);
                        MMA_F16(oacc[mt][nt][0],oacc[mt][nt][1],oacc[mt][nt][2],oacc[mt][nt][3],
                                ua[mt][1][0],ua[mt][1][1],ua[mt][1][2],ua[mt][1][3], b2,b3);
                    }
                }
            }
            const int sbase = (32 - 32*wr + kb) & 127;
            #pragma unroll
            for (int ksp = 0; ksp < 3; ksp++) {
                uint32_t ua[2][2][4];
                #pragma unroll
                for (int mt = 0; mt < 2; mt++)
                    #pragma unroll
                    for (int kk = 0; kk < 2; kk++) {
                        uint32_t ad = s2u(Bw + (wr*32 + mt*16 + l15)*SBW + (2*ksp+kk)*16 + lq16);
                        LDSM_X4(ua[mt][kk][0], ua[mt][kk][1], ua[mt][kk][2], ua[mt][kk][3], ad);
                    }
                const int colr = (sbase + ksp*32 + lq8) & 127;
                #pragma unroll
                for (int nt = 0; nt < 2; nt++) {
                    uint32_t b0,b1,b2,b3;
                    uint32_t ad = s2u(Tvwt + (wc*16 + nt*8 + l7)*SH2 + colr);
                    LDSM_X4(b0,b1,b2,b3, ad);
                    #pragma unroll
                    for (int mt = 0; mt < 2; mt++) {
                        MMA_F16(oacc[mt][nt][0],oacc[mt][nt][1],oacc[mt][nt][2],oacc[mt][nt][3],
                                ua[mt][0][0],ua[mt][0][1],ua[mt][0][2],ua[mt][0][3], b0,b1);
                        MMA_F16(oacc[mt][nt][0],oacc[mt][nt][1],oacc[mt][nt][2],oacc[mt][nt][3],
                                ua[mt][1][0],ua[mt][1][1],ua[mt][1][2],ua[mt][1][3], b2,b3);
                    }
                }
            }
        }
        __syncthreads();
    }

    // ---- epilogue ----
    #pragma unroll
    for (int mt = 0; mt < 2; mt++) {
        const int rowa = wr*32 + mt*16 + g;
        const int rowb = rowa + 8;
        const float la = 1.0f / lrowS[rowa];
        const float lb = 1.0f / lrowS[rowb];
        const size_t basea = (((size_t)((b*LL + q0 + rowa)*HH + h)) << 6);
        const size_t baseb = (((size_t)((b*LL + q0 + rowb)*HH + h)) << 6);
        #pragma unroll
        for (int nt = 0; nt < 2; nt++) {
            int c = wc*16 + nt*8 + 2*t;
            __half2 h0 = __floats2half2_rn(oacc[mt][nt][0]*la, oacc[mt][nt][1]*la);
            __half2 h1 = __floats2half2_rn(oacc[mt][nt][2]*lb, oacc[mt][nt][3]*lb);
            *(uint32_t*)(g_ctx + basea + c) = *(uint32_t*)&h0;
            *(uint32_t*)(g_ctx + baseb + c) = *(uint32_t*)&h1;
        }
    }
}

// ---------------------------------------------------------------------------
// Final FC, fp16 mma, 128x128 tiles, 512 threads, 2 CTAs/SM, reg prefetch.
// ---------------------------------------------------------------------------
__global__ __launch_bounds__(512, 2) void fc_kernel(
    const float* __restrict__ bfc, float* __restrict__ out)
{
    __shared__ __half Xs[128*SH];
    __shared__ __half Ws[128*SH];

    const int tid  = threadIdx.x;
    const int warp = tid >> 5, lane = tid & 31;
    const int g = lane >> 2, t = lane & 3;
    const int wr = warp >> 2, wc = warp & 3;
    const size_t r0 = (size_t)blockIdx.x * 128;
    const size_t n0 = (size_t)blockIdx.y * 128;

    const int rrA = tid >> 3,         ccA = (tid & 7) << 3;
    const int rrB = (tid + 512) >> 3, ccB = ((tid + 512) & 7) << 3;

    float oacc[2][4][4] = {};
    uint4 pX[2], pW[2];

    *(uint4*)&Xs[rrA*SH + ccA] = *(const uint4*)(g_ctx   + (r0 + rrA)*EMBN + ccA);
    *(uint4*)&Xs[rrB*SH + ccB] = *(const uint4*)(g_ctx   + (r0 + rrB)*EMBN + ccB);
    *(uint4*)&Ws[rrA*SH + ccA] = *(const uint4*)(g_Wfc_h + (n0 + rrA)*EMBN + ccA);
    *(uint4*)&Ws[rrB*SH + ccB] = *(const uint4*)(g_Wfc_h + (n0 + rrB)*EMBN + ccB);

    for (int e = 0; e < 16; e++) {
        __syncthreads();
        if (e < 15) {
            const int e0n = (e + 1) * 64;
            pX[0] = *(const uint4*)(g_ctx   + (r0 + rrA)*EMBN + e0n + ccA);
            pX[1] = *(const uint4*)(g_ctx   + (r0 + rrB)*EMBN + e0n + ccB);
            pW[0] = *(const uint4*)(g_Wfc_h + (n0 + rrA)*EMBN + e0n + ccA);
            pW[1] = *(const uint4*)(g_Wfc_h + (n0 + rrB)*EMBN + e0n + ccB);
        }
        #pragma unroll
        for (int ks = 0; ks < 4; ks++) {
            uint32_t a[2][4];
            #pragma unroll
            for (int mi = 0; mi < 2; mi++) {
                int ar = wr*32 + mi*16 + g;
                a[mi][0] = ldh2(&Xs[ ar   *SH + ks*16 + 2*t    ]);
                a[mi][1] = ldh2(&Xs[(ar+8)*SH + ks*16 + 2*t    ]);
                a[mi][2] = ldh2(&Xs[ ar   *SH + ks*16 + 2*t + 8]);
                a[mi][3] = ldh2(&Xs[(ar+8)*SH + ks*16 + 2*t + 8]);
            }
            #pragma unroll
            for (int nt = 0; nt < 4; nt++) {
                const __half* Bb = Ws + (wc*32 + nt*8 + g)*SH;
                uint32_t b0 = ldh2(Bb + ks*16 + 2*t);
                uint32_t b1 = ldh2(Bb + ks*16 + 2*t + 8);
                #pragma unroll
                for (int mi = 0; mi < 2; mi++)
                    MMA_F16(oacc[mi][nt][0], oacc[mi][nt][1], oacc[mi][nt][2], oacc[mi][nt][3],
                            a[mi][0], a[mi][1], a[mi][2], a[mi][3], b0, b1);
            }
        }
        __syncthreads();
        if (e < 15) {
            *(uint4*)&Xs[rrA*SH + ccA] = pX[0];
            *(uint4*)&Xs[rrB*SH + ccB] = pX[1];
            *(uint4*)&Ws[rrA*SH + ccA] = pW[0];
            *(uint4*)&Ws[rrB*SH + ccB] = pW[1];
        }
    }

    #pragma unroll
    for (int mi = 0; mi < 2; mi++) {
        size_t ra = r0 + wr*32 + mi*16 + g;
        #pragma unroll
        for (int nt = 0; nt < 4; nt++) {
            size_t c = n0 + wc*32 + nt*8 + 2*t;
            float bv0 = bfc[c], bv1 = bfc[c+1];
            *(float2*)(out + ra*EMBN + c) =
                make_float2(oacc[mi][nt][0] + bv0, oacc[mi][nt][1] + bv1);
            *(float2*)(out + (ra+8)*EMBN + c) =
                make_float2(oacc[mi][nt][2] + bv0, oacc[mi][nt][3] + bv1);
        }
    }
}

// ---------------------------------------------------------------------------
extern "C" void kernel_launch(void* const* d_in, const int* in_sizes, int n_in,
                              void* d_out, int out_size)
{
    const float* query = (const float*)d_in[0];
    const float* key_  = (const float*)d_in[1];
    const float* value = (const float*)d_in[2];
    const int*   mask  = (const int*)d_in[3];
    const float* Wq = (const float*)d_in[4];
    const float* bq = (const float*)d_in[5];
    const float* Wk = (const float*)d_in[6];
    const float* bk = (const float*)d_in[7];
    const float* Wv = (const float*)d_in[8];
    const float* bv = (const float*)d_in[9];
    const float* Wfc = (const float*)d_in[10];
    const float* bfc = (const float*)d_in[11];
    const float* relk = (const float*)d_in[12];
    const float* relv = (const float*)d_in[13];
    float* out = (float*)d_out;

    cudaFuncSetAttribute(attn_kernel, cudaFuncAttributeMaxDynamicSharedMemorySize, ATT_SMEM_BYTES);

    pre_kernel<<<dim3(1024, 4, 1), 256>>>(query, key_, value, Wq, bq, Wk, bk, Wv, bv,
                                          relk, relv, Wfc, mask);
    attn_kernel<<<dim3(16, 16, 4), 256, ATT_SMEM_BYTES>>>();
    fc_kernel<<<dim3(32, 8, 1), 512>>>(bfc, out);
}

// round 11
// speedup vs baseline: 1.7589x; 1.2830x over previous
#include <cuda_runtime.h>
#include <cuda_fp16.h>
#include <cstdint>
#include <cstddef>

#define BB   4
#define LL   1024
#define HH   16
#define DD   64
#define EMBN 1024
#define MAXREL 512
#define NREL (2*MAXREL + 1)

#define QB   128
#define SH   72    // half stride, 64-wide buffers (36 words == 4 mod 32)
#define SBW  88    // half stride, band/Q buffer  (44 words == 12 mod 32)
#define SRS  264   // half stride, Srel ring      (132 words == 4 mod 32)
#define NEGBIG (-1.25e19f)

// Scratch (allocation-free rule: device globals)
__device__ __half g_qh [BB*LL*HH*DD];
__device__ __half g_kh [BB*LL*HH*DD];
__device__ __half g_vh [BB*LL*HH*DD];
__device__ __half g_ctx[BB*LL*HH*DD];
__device__ __half g_relk_h[NREL*DD];
__device__ __half g_relv_h[NREL*DD];
__device__ __half g_Wfc_h[EMBN*EMBN];
__device__ unsigned long long g_maskb[BB*LL*16];   // 64 k-bits per (row, k-tile)

// ---------------------------------------------------------------------------
#define MMA_F16(d0,d1,d2,d3,a0,a1,a2,a3,b0,b1)                               \
    asm volatile("mma.sync.aligned.m16n8k16.row.col.f32.f16.f16.f32 "        \
                 "{%0,%1,%2,%3}, {%4,%5,%6,%7}, {%8,%9}, {%0,%1,%2,%3};"     \
                 : "+f"(d0), "+f"(d1), "+f"(d2), "+f"(d3)                    \
                 : "r"(a0), "r"(a1), "r"(a2), "r"(a3), "r"(b0), "r"(b1))

#define LDSM_X4(r0,r1,r2,r3,addr)                                            \
    asm volatile("ldmatrix.sync.aligned.m8n8.x4.shared.b16 {%0,%1,%2,%3}, [%4];" \
                 : "=r"(r0), "=r"(r1), "=r"(r2), "=r"(r3) : "r"(addr) : "memory")

#define LDSM_X4_T(r0,r1,r2,r3,addr)                                          \
    asm volatile("ldmatrix.sync.aligned.m8n8.x4.trans.shared.b16 {%0,%1,%2,%3}, [%4];" \
                 : "=r"(r0), "=r"(r1), "=r"(r2), "=r"(r3) : "r"(addr) : "memory")

#define STSM_X4(addr,r0,r1,r2,r3)                                            \
    asm volatile("stmatrix.sync.aligned.m8n8.x4.shared.b16 [%0], {%1,%2,%3,%4};" \
                 :: "r"(addr), "r"(r0), "r"(r1), "r"(r2), "r"(r3) : "memory")

#define CP16(dst,src)                                                        \
    asm volatile("cp.async.cg.shared.global [%0], [%1], 16;" :: "r"(dst), "l"(src))
#define CPCOMMIT()  asm volatile("cp.async.commit_group;")
#define CPWAITALL() asm volatile("cp.async.wait_group 0;" ::: "memory")

__device__ __forceinline__ uint32_t ldh2(const __half* p) { return *(const uint32_t*)p; }
__device__ __forceinline__ uint32_t s2u(const void* p) {
    return (uint32_t)__cvta_generic_to_shared(p);
}
__device__ __forceinline__ int clampdiff(int d) {
    return d < -MAXREL ? -MAXREL : (d > MAXREL ? MAXREL : d);
}
__device__ __forceinline__ uint2 f4_to_h4(float4 v) {
    __half2 h0 = __floats2half2_rn(v.x, v.y);
    __half2 h1 = __floats2half2_rn(v.z, v.w);
    uint2 r; r.x = *(uint32_t*)&h0; r.y = *(uint32_t*)&h1; return r;
}
__device__ __forceinline__ uint32_t h2u(__half2 h) { return *(uint32_t*)&h; }

// ---------------------------------------------------------------------------
// Pre: projections via fp16 mma (y=0..2; Q pre-scaled 0.125) + constants (y=3)
// ---------------------------------------------------------------------------
__global__ __launch_bounds__(256) void pre_kernel(
    const float* __restrict__ query, const float* __restrict__ key_, const float* __restrict__ value,
    const float* __restrict__ Wq, const float* __restrict__ bq,
    const float* __restrict__ Wk, const float* __restrict__ bk,
    const float* __restrict__ Wv, const float* __restrict__ bv,
    const float* __restrict__ relk, const float* __restrict__ relv,
    const float* __restrict__ Wfc,  const int* __restrict__ mask)
{
    const int tid = threadIdx.x;

    if (blockIdx.y == 3) {
        const int stride = 1024 * 256;
        const int base = blockIdx.x * 256 + tid;
        for (int i = base; i < NREL*DD; i += stride) {
            g_relk_h[i] = __float2half_rn(relk[i]);
            g_relv_h[i] = __float2half_rn(relv[i]);
        }
        for (int i = base; i < EMBN*EMBN; i += stride)
            g_Wfc_h[i] = __float2half_rn(Wfc[i]);
        for (int i = base; i < BB*LL*16; i += stride) {
            int row = i >> 4, w = i & 15;
            const int* mrow = mask + (size_t)row*LL + w*64;
            unsigned long long bits = 0ull;
            #pragma unroll
            for (int j = 0; j < 16; j++) {
                int4 v = *(const int4*)(mrow + j*4);
                bits |= (unsigned long long)(v.x != 0) << (4*j + 0);
                bits |= (unsigned long long)(v.y != 0) << (4*j + 1);
                bits |= (unsigned long long)(v.z != 0) << (4*j + 2);
                bits |= (unsigned long long)(v.w != 0) << (4*j + 3);
            }
            g_maskb[i] = bits;
        }
        return;
    }

    __shared__ __half Xs[64*SH];
    __shared__ __half Ws[64*SH];
    __shared__ float bs[64];

    const float* X; const float* W; const float* bias; __half* out;
    float oscale = 1.0f;
    if (blockIdx.y == 0)      { X = query; W = Wq; bias = bq; out = g_qh; oscale = 0.125f; }
    else if (blockIdx.y == 1) { X = key_;  W = Wk; bias = bk; out = g_kh; }
    else                      { X = value; W = Wv; bias = bv; out = g_vh; }

    const size_t r0 = (size_t)blockIdx.x * 64;
    const int warp = tid >> 5, lane = tid & 31;
    const int g = lane >> 2, t = lane & 3;
    const int wr = warp >> 2, wc = warp & 3;
    const int l7 = lane & 7, l15 = lane & 15;
    const int lq8 = (lane >> 3) << 3;
    const int lq16 = (lane >> 4) << 3;

    {
        const int rr = tid >> 2, cb = (tid & 3) << 4;
        #pragma unroll
        for (int i = 0; i < 4; i++) {
            float4 v = *(const float4*)(X + (r0 + rr)*64 + cb + i*4);
            *(uint2*)&Xs[rr*SH + cb + i*4] = f4_to_h4(v);
            float4 w = *(const float4*)(W + (size_t)rr*64 + cb + i*4);
            *(uint2*)&Ws[rr*SH + cb + i*4] = f4_to_h4(w);
        }
    }
    if (tid < 64) bs[tid] = bias[tid];
    __syncthreads();

    uint32_t qa[2][4][4];
    #pragma unroll
    for (int mt = 0; mt < 2; mt++)
        #pragma unroll
        for (int ks = 0; ks < 4; ks++) {
            uint32_t ad = s2u(Xs + (wr*32 + mt*16 + l15)*SH + ks*16 + lq16);
            LDSM_X4(qa[mt][ks][0], qa[mt][ks][1], qa[mt][ks][2], qa[mt][ks][3], ad);
        }

    #pragma unroll
    for (int nt = 0; nt < 2; nt++) {
        float c0[4] = {0,0,0,0}, c1[4] = {0,0,0,0};
        #pragma unroll
        for (int ksp = 0; ksp < 2; ksp++) {
            uint32_t b0,b1,b2,b3;
            uint32_t ad = s2u(Ws + (wc*16 + nt*8 + l7)*SH + ksp*32 + lq8);
            LDSM_X4(b0,b1,b2,b3, ad);
            MMA_F16(c0[0],c0[1],c0[2],c0[3], qa[0][2*ksp  ][0],qa[0][2*ksp  ][1],qa[0][2*ksp  ][2],qa[0][2*ksp  ][3], b0,b1);
            MMA_F16(c1[0],c1[1],c1[2],c1[3], qa[1][2*ksp  ][0],qa[1][2*ksp  ][1],qa[1][2*ksp  ][2],qa[1][2*ksp  ][3], b0,b1);
            MMA_F16(c0[0],c0[1],c0[2],c0[3], qa[0][2*ksp+1][0],qa[0][2*ksp+1][1],qa[0][2*ksp+1][2],qa[0][2*ksp+1][3], b2,b3);
            MMA_F16(c1[0],c1[1],c1[2],c1[3], qa[1][2*ksp+1][0],qa[1][2*ksp+1][1],qa[1][2*ksp+1][2],qa[1][2*ksp+1][3], b2,b3);
        }
        const int cb2 = wc*16 + nt*8 + 2*t;
        const float bv0 = bs[cb2], bv1 = bs[cb2 + 1];
        __half2 h00 = __floats2half2_rn((c0[0] + bv0)*oscale, (c0[1] + bv1)*oscale);
        __half2 h01 = __floats2half2_rn((c0[2] + bv0)*oscale, (c0[3] + bv1)*oscale);
        __half2 h10 = __floats2half2_rn((c1[0] + bv0)*oscale, (c1[1] + bv1)*oscale);
        __half2 h11 = __floats2half2_rn((c1[2] + bv0)*oscale, (c1[3] + bv1)*oscale);
        *(uint32_t*)(out + (r0 + wr*32      + g)*64 + cb2) = h2u(h00);
        *(uint32_t*)(out + (r0 + wr*32 +  8 + g)*64 + cb2) = h2u(h01);
        *(uint32_t*)(out + (r0 + wr*32 + 16 + g)*64 + cb2) = h2u(h10);
        *(uint32_t*)(out + (r0 + wr*32 + 24 + g)*64 + cb2) = h2u(h11);
    }
}

// ---------------------------------------------------------------------------
// Attention, flash-v2: QB=128, 8 warps x m16 (full rows), warp-local softmax,
// C->A register reuse for PV, stmatrix Srel ring (mod 4), constant-shift band,
// ldmatrix.trans for V/relV, cp.async double-buffered, 1 syncthreads/tile.
// ---------------------------------------------------------------------------
#define ATT_SMEM_HALFS (128*SRS + 128*SBW + 2*64*SH + 2*64*SH + 2*64*SH + 4*64*SH)
#define ATT_SMEM_BYTES (ATT_SMEM_HALFS*2)

__device__ __forceinline__ void srel_block_gemm(
    const __half* Tk, __half* SrelH, const uint32_t qa[4][4],
    int rw, int pbS, int lane)
{
    const int l7 = lane & 7, l15 = lane & 15;
    const int lq8 = (lane >> 3) << 3;
    const int lq16 = (lane >> 4) << 3;
    #pragma unroll
    for (int npp = 0; npp < 4; npp++) {
        float c0[4] = {0,0,0,0}, c1[4] = {0,0,0,0};
        #pragma unroll
        for (int ksp = 0; ksp < 2; ksp++) {
            uint32_t b0,b1,b2,b3;
            uint32_t ad = s2u(Tk + (npp*16 + l7)*SH + ksp*32 + lq8);
            LDSM_X4(b0,b1,b2,b3, ad);
            MMA_F16(c0[0],c0[1],c0[2],c0[3], qa[2*ksp  ][0],qa[2*ksp  ][1],qa[2*ksp  ][2],qa[2*ksp  ][3], b0,b1);
            MMA_F16(c0[0],c0[1],c0[2],c0[3], qa[2*ksp+1][0],qa[2*ksp+1][1],qa[2*ksp+1][2],qa[2*ksp+1][3], b2,b3);
            uint32_t ad2 = s2u(Tk + (npp*16 + 8 + l7)*SH + ksp*32 + lq8);
            LDSM_X4(b0,b1,b2,b3, ad2);
            MMA_F16(c1[0],c1[1],c1[2],c1[3], qa[2*ksp  ][0],qa[2*ksp  ][1],qa[2*ksp  ][2],qa[2*ksp  ][3], b0,b1);
            MMA_F16(c1[0],c1[1],c1[2],c1[3], qa[2*ksp+1][0],qa[2*ksp+1][1],qa[2*ksp+1][2],qa[2*ksp+1][3], b2,b3);
        }
        __half2 h0 = __floats2half2_rn(c0[0], c0[1]);
        __half2 h1 = __floats2half2_rn(c0[2], c0[3]);
        __half2 h2 = __floats2half2_rn(c1[0], c1[1]);
        __half2 h3 = __floats2half2_rn(c1[2], c1[3]);
        uint32_t sad = s2u(SrelH + (rw + l15)*SRS + pbS + npp*16 + lq16);
        STSM_X4(sad, h2u(h0), h2u(h1), h2u(h2), h2u(h3));
    }
}

__global__ __launch_bounds__(256, 1) void attn_kernel()
{
    extern __shared__ __half smh[];
    __half* SrelH = smh;                     // 128 x SRS  rel-score ring (256 slots)
    __half* Bw    = SrelH + 128*SRS;         // 128 x SBW  Q staging, then band (K=80)
    __half* KhB   = Bw    + 128*SBW;         // 2 x 64 x SH  [k][e]
    __half* VhB   = KhB   + 2*64*SH;         // 2 x 64 x SH  [k][d]
    __half* TkB   = VhB   + 2*64*SH;         // 2 x 64 x SH  new relK block [j][e]
    __half* TrvB  = TkB   + 2*64*SH;         // 4 x 64 x SH  relV ring [diff][d]

    const int b  = blockIdx.z;
    const int h  = blockIdx.y;
    const int q0 = blockIdx.x * QB;
    const int tid  = threadIdx.x;
    const int warp = tid >> 5, lane = tid & 31;
    const int g = lane >> 2, t = lane & 3;
    const int l7 = lane & 7, l15 = lane & 15;
    const int lq8  = (lane >> 3) << 3;
    const int lq16 = (lane >> 4) << 3;
    const int tkk = ((lane >> 3) & 1) << 3;   // trans k-half
    const int tnn = (lane >> 4) << 3;         // trans n-half
    const int rw = warp * 16;

    // staging coords: 256 threads cover 32 rows x 64 cols per CP16 -> 2 per tile
    const int srow = tid >> 3, scol8 = (tid & 7) << 3;
    const int d00 = -q0;

    // ---------------- prologue ----------------
    // Q -> Bw (128 rows)
    #pragma unroll
    for (int i = 0; i < 4; i++) {
        int id = tid + i*256;
        int r = id >> 3, c = (id & 7) << 3;
        CP16(s2u(Bw + r*SBW + c),
             g_qh + (((size_t)((b*LL + q0 + r)*HH + h)) << 6) + c);
    }
    // K0 / V0 (64 rows each = 2 CP16/thread)
    #pragma unroll
    for (int half2x = 0; half2x < 2; half2x++) {
        int r = srow + half2x*32;
        CP16(s2u(KhB + r*SH + scol8),
             g_kh + (((size_t)((b*LL + r)*HH + h)) << 6) + scol8);
        CP16(s2u(VhB + r*SH + scol8),
             g_vh + (((size_t)((b*LL + r)*HH + h)) << 6) + scol8);
    }
    // relK history blocks d00-128 -> TkB[0], d00-64 -> TkB[1]
    #pragma unroll
    for (int half2x = 0; half2x < 2; half2x++) {
        int r = srow + half2x*32;
        int dfA = clampdiff(d00 - 128 + r);
        CP16(s2u(TkB + r*SH + scol8),
             g_relk_h + ((size_t)(dfA + MAXREL) << 6) + scol8);
        int dfB = clampdiff(d00 - 64 + r);
        CP16(s2u(TkB + 64*SH + r*SH + scol8),
             g_relk_h + ((size_t)(dfB + MAXREL) << 6) + scol8);
    }
    // relV blocks d00-128, d00-64, d00 into mod-4 ring
    #pragma unroll
    for (int bl = 0; bl < 3; bl++) {
        int base = d00 - 128 + bl*64;
        int pb = ((base + 2048) >> 6) & 3;
        #pragma unroll
        for (int half2x = 0; half2x < 2; half2x++) {
            int r = srow + half2x*32;
            int df = clampdiff(base + r);
            CP16(s2u(TrvB + (pb*64 + r)*SH + scol8),
                 g_relv_h + ((size_t)(df + MAXREL) << 6) + scol8);
        }
    }
    CPCOMMIT(); CPWAITALL();
    __syncthreads();

    // Q fragments
    uint32_t qa[4][4];
    #pragma unroll
    for (int ks = 0; ks < 4; ks++) {
        uint32_t ad = s2u(Bw + (rw + l15)*SBW + ks*16 + lq16);
        LDSM_X4(qa[ks][0], qa[ks][1], qa[ks][2], qa[ks][3], ad);
    }
    __syncthreads();   // all Q frags read -> Bw reusable

    // zero band buffer once (margins stay zero; valid slots rewritten each tile)
    {
        const uint4 z = make_uint4(0,0,0,0);
        for (int i = tid; i < 128*SBW/8; i += 256) ((uint4*)Bw)[i] = z;
    }

    // history Srel blocks
    srel_block_gemm(TkB,         SrelH, qa, rw, (((d00 - 128 + 2048) >> 6) & 3)*64, lane);
    srel_block_gemm(TkB + 64*SH, SrelH, qa, rw, (((d00 -  64 + 2048) >> 6) & 3)*64, lane);
    __syncthreads();   // all warps done with TkB before restage; band zero visible

    // restage TkB[0] with block d00 (used at kt = 0)
    #pragma unroll
    for (int half2x = 0; half2x < 2; half2x++) {
        int r = srow + half2x*32;
        int df = clampdiff(d00 + r);
        CP16(s2u(TkB + r*SH + scol8),
             g_relk_h + ((size_t)(df + MAXREL) << 6) + scol8);
    }
    CPCOMMIT(); CPWAITALL();
    __syncthreads();

    // ---------------- main loop ----------------
    float oacc[8][4] = {};
    float m0 = -1e30f, m1 = -1e30f, l0 = 0.f, l1 = 0.f;

    for (int kt = 0; kt < 16; kt++) {
        const int k0 = kt * 64;
        const int d0 = k0 - q0;
        const int cs = kt & 1, ns = cs ^ 1;

        unsigned long long bits0 = g_maskb[((size_t)(b*LL + q0 + rw + g    ) << 4) + kt];
        unsigned long long bits1 = g_maskb[((size_t)(b*LL + q0 + rw + g + 8) << 4) + kt];

        // cp.async staging for tile kt+1
        if (kt < 15) {
            const int k0n = k0 + 64, dn = d0 + 64;
            const int pbn = ((dn + 2048) >> 6) & 3;
            #pragma unroll
            for (int half2x = 0; half2x < 2; half2x++) {
                int r = srow + half2x*32;
                CP16(s2u(KhB + ns*64*SH + r*SH + scol8),
                     g_kh + (((size_t)((b*LL + k0n + r)*HH + h)) << 6) + scol8);
                CP16(s2u(VhB + ns*64*SH + r*SH + scol8),
                     g_vh + (((size_t)((b*LL + k0n + r)*HH + h)) << 6) + scol8);
                int df = clampdiff(dn + r);
                CP16(s2u(TkB + ns*64*SH + r*SH + scol8),
                     g_relk_h + ((size_t)(df + MAXREL) << 6) + scol8);
                CP16(s2u(TrvB + (pbn*64 + r)*SH + scol8),
                     g_relv_h + ((size_t)(df + MAXREL) << 6) + scol8);
            }
            CPCOMMIT();
        }

        // ---- GEMM1a: QK scores -> registers ----
        float s[8][4] = {};
        #pragma unroll
        for (int np = 0; np < 8; np++) {
            #pragma unroll
            for (int ksp = 0; ksp < 2; ksp++) {
                uint32_t b0,b1,b2,b3;
                uint32_t ad = s2u(KhB + cs*64*SH + (np*8 + l7)*SH + ksp*32 + lq8);
                LDSM_X4(b0,b1,b2,b3, ad);
                MMA_F16(s[np][0],s[np][1],s[np][2],s[np][3],
                        qa[2*ksp  ][0],qa[2*ksp  ][1],qa[2*ksp  ][2],qa[2*ksp  ][3], b0,b1);
                MMA_F16(s[np][0],s[np][1],s[np][2],s[np][3],
                        qa[2*ksp+1][0],qa[2*ksp+1][1],qa[2*ksp+1][2],qa[2*ksp+1][3], b2,b3);
            }
        }
        // ---- GEMM1b: new rel block -> SrelH ring ----
        srel_block_gemm(TkB + cs*64*SH, SrelH, qa, rw,
                        (((d0 + 2048) >> 6) & 3)*64, lane);
        __syncwarp();

        // ---- softmax (warp-local) ----
        #pragma unroll
        for (int np = 0; np < 8; np++) {
            #pragma unroll
            for (int i = 0; i < 2; i++) {
                const int c = np*8 + 2*t + i;
                int dd2a = d0 + c - rw - g + 2048;
                int sla = ((dd2a >> 6) & 3)*64 + (dd2a & 63);
                float rel0 = __half2float(SrelH[(rw + g)*SRS + sla]);
                int dd2b = dd2a - 8;
                int slb = ((dd2b >> 6) & 3)*64 + (dd2b & 63);
                float rel1 = __half2float(SrelH[(rw + g + 8)*SRS + slb]);
                float v0 = ((bits0 >> c) & 1ull) ? s[np][i]     : NEGBIG;
                float v1 = ((bits1 >> c) & 1ull) ? s[np][2 + i] : NEGBIG;
                s[np][i]     = v0 + rel0;
                s[np][2 + i] = v1 + rel1;
            }
        }
        float rm0 = -1e30f, rm1 = -1e30f;
        #pragma unroll
        for (int np = 0; np < 8; np++) {
            rm0 = fmaxf(rm0, fmaxf(s[np][0], s[np][1]));
            rm1 = fmaxf(rm1, fmaxf(s[np][2], s[np][3]));
        }
        rm0 = fmaxf(rm0, __shfl_xor_sync(0xffffffffu, rm0, 1));
        rm0 = fmaxf(rm0, __shfl_xor_sync(0xffffffffu, rm0, 2));
        rm1 = fmaxf(rm1, __shfl_xor_sync(0xffffffffu, rm1, 1));
        rm1 = fmaxf(rm1, __shfl_xor_sync(0xffffffffu, rm1, 2));
        float mn0 = fmaxf(m0, rm0), mn1 = fmaxf(m1, rm1);
        float csc0 = __expf(m0 - mn0), csc1 = __expf(m1 - mn1);
        m0 = mn0; m1 = mn1;
        float ls0 = 0.f, ls1 = 0.f;
        #pragma unroll
        for (int np = 0; np < 8; np++) {
            s[np][0] = __expf(s[np][0] - mn0); ls0 += s[np][0];
            s[np][1] = __expf(s[np][1] - mn0); ls0 += s[np][1];
            s[np][2] = __expf(s[np][2] - mn1); ls1 += s[np][2];
            s[np][3] = __expf(s[np][3] - mn1); ls1 += s[np][3];
        }
        ls0 += __shfl_xor_sync(0xffffffffu, ls0, 1);
        ls0 += __shfl_xor_sync(0xffffffffu, ls0, 2);
        ls1 += __shfl_xor_sync(0xffffffffu, ls1, 1);
        ls1 += __shfl_xor_sync(0xffffffffu, ls1, 2);
        l0 = l0*csc0 + ls0;
        l1 = l1*csc1 + ls1;
        #pragma unroll
        for (int np = 0; np < 8; np++) {
            oacc[np][0] *= csc0; oacc[np][1] *= csc0;
            oacc[np][2] *= csc1; oacc[np][3] *= csc1;
        }

        // P -> A fragments (register reuse) + band scatter
        uint32_t pa[4][4];
        #pragma unroll
        for (int ks = 0; ks < 4; ks++) {
            pa[ks][0] = h2u(__floats2half2_rn(s[2*ks  ][0], s[2*ks  ][1]));
            pa[ks][1] = h2u(__floats2half2_rn(s[2*ks  ][2], s[2*ks  ][3]));
            pa[ks][2] = h2u(__floats2half2_rn(s[2*ks+1][0], s[2*ks+1][1]));
            pa[ks][3] = h2u(__floats2half2_rn(s[2*ks+1][2], s[2*ks+1][3]));
        }
        #pragma unroll
        for (int np = 0; np < 8; np++) {
            #pragma unroll
            for (int i = 0; i < 2; i++) {
                const int c = np*8 + 2*t + i;
                Bw[(rw + g    )*SBW + c - g + 15] = __float2half_rn(s[np][i]);
                Bw[(rw + g + 8)*SBW + c - g +  7] = __float2half_rn(s[np][2 + i]);
            }
        }
        __syncwarp();

        // ---- GEMM2a: PV (B via ldmatrix.trans on [k][d]) ----
        #pragma unroll
        for (int ks = 0; ks < 4; ks++) {
            #pragma unroll
            for (int ndc = 0; ndc < 4; ndc++) {
                uint32_t b0,b1,b2,b3;
                uint32_t ad = s2u(VhB + cs*64*SH + (ks*16 + tkk + l7)*SH + ndc*16 + tnn);
                LDSM_X4_T(b0,b1,b2,b3, ad);
                MMA_F16(oacc[2*ndc  ][0],oacc[2*ndc  ][1],oacc[2*ndc  ][2],oacc[2*ndc  ][3],
                        pa[ks][0],pa[ks][1],pa[ks][2],pa[ks][3], b0,b1);
                MMA_F16(oacc[2*ndc+1][0],oacc[2*ndc+1][1],oacc[2*ndc+1][2],oacc[2*ndc+1][3],
                        pa[ks][0],pa[ks][1],pa[ks][2],pa[ks][3], b2,b3);
            }
        }
        // ---- GEMM2b: band @ relV ring (K=80, per-warp diff base) ----
        #pragma unroll
        for (int ks = 0; ks < 5; ks++) {
            uint32_t ua0,ua1,ua2,ua3;
            uint32_t aad = s2u(Bw + (rw + l15)*SBW + ks*16 + lq16);
            LDSM_X4(ua0,ua1,ua2,ua3, aad);
            int dd = d0 - 15 - rw + ks*16 + tkk + l7;
            if (dd > d0 + 63) dd = d0 + 63;       // slot 79 is always zero
            int dd2 = dd + 2048;
            int prow = ((dd2 >> 6) & 3)*64 + (dd2 & 63);
            const __half* Bb = TrvB + prow*SH + tnn;
            #pragma unroll
            for (int ndc = 0; ndc < 4; ndc++) {
                uint32_t b0,b1,b2,b3;
                LDSM_X4_T(b0,b1,b2,b3, s2u(Bb + ndc*16));
                MMA_F16(oacc[2*ndc  ][0],oacc[2*ndc  ][1],oacc[2*ndc  ][2],oacc[2*ndc  ][3],
                        ua0,ua1,ua2,ua3, b0,b1);
                MMA_F16(oacc[2*ndc+1][0],oacc[2*ndc+1][1],oacc[2*ndc+1][2],oacc[2*ndc+1][3],
                        ua0,ua1,ua2,ua3, b2,b3);
            }
        }

        CPWAITALL();
        __syncthreads();
    }

    // ---- epilogue ----
    {
        const float inv0 = 1.0f / l0;
        const float inv1 = 1.0f / l1;
        const size_t base0 = (((size_t)((b*LL + q0 + rw + g    )*HH + h)) << 6);
        const size_t base1 = (((size_t)((b*LL + q0 + rw + g + 8)*HH + h)) << 6);
        #pragma unroll
        for (int np = 0; np < 8; np++) {
            const int c = np*8 + 2*t;
            __half2 h0 = __floats2half2_rn(oacc[np][0]*inv0, oacc[np][1]*inv0);
            __half2 h1 = __floats2half2_rn(oacc[np][2]*inv1, oacc[np][3]*inv1);
            *(uint32_t*)(g_ctx + base0 + c) = h2u(h0);
            *(uint32_t*)(g_ctx + base1 + c) = h2u(h1);
        }
    }
}

// ---------------------------------------------------------------------------
// Final FC, fp16 mma, 128x128 tiles, 512 threads, 2 CTAs/SM, reg prefetch.
// ---------------------------------------------------------------------------
__global__ __launch_bounds__(512, 2) void fc_kernel(
    const float* __restrict__ bfc, float* __restrict__ out)
{
    __shared__ __half Xs[128*SH];
    __shared__ __half Ws[128*SH];

    const int tid  = threadIdx.x;
    const int warp = tid >> 5, lane = tid & 31;
    const int g = lane >> 2, t = lane & 3;
    const int wr = warp >> 2, wc = warp & 3;
    const size_t r0 = (size_t)blockIdx.x * 128;
    const size_t n0 = (size_t)blockIdx.y * 128;

    const int rrA = tid >> 3,         ccA = (tid & 7) << 3;
    const int rrB = (tid + 512) >> 3, ccB = ((tid + 512) & 7) << 3;

    float oacc[2][4][4] = {};
    uint4 pX[2], pW[2];

    *(uint4*)&Xs[rrA*SH + ccA] = *(const uint4*)(g_ctx   + (r0 + rrA)*EMBN + ccA);
    *(uint4*)&Xs[rrB*SH + ccB] = *(const uint4*)(g_ctx   + (r0 + rrB)*EMBN + ccB);
    *(uint4*)&Ws[rrA*SH + ccA] = *(const uint4*)(g_Wfc_h + (n0 + rrA)*EMBN + ccA);
    *(uint4*)&Ws[rrB*SH + ccB] = *(const uint4*)(g_Wfc_h + (n0 + rrB)*EMBN + ccB);

    for (int e = 0; e < 16; e++) {
        __syncthreads();
        if (e < 15) {
            const int e0n = (e + 1) * 64;
            pX[0] = *(const uint4*)(g_ctx   + (r0 + rrA)*EMBN + e0n + ccA);
            pX[1] = *(const uint4*)(g_ctx   + (r0 + rrB)*EMBN + e0n + ccB);
            pW[0] = *(const uint4*)(g_Wfc_h + (n0 + rrA)*EMBN + e0n + ccA);
            pW[1] = *(const uint4*)(g_Wfc_h + (n0 + rrB)*EMBN + e0n + ccB);
        }
        #pragma unroll
        for (int ks = 0; ks < 4; ks++) {
            uint32_t a[2][4];
            #pragma unroll
            for (int mi = 0; mi < 2; mi++) {
                int ar = wr*32 + mi*16 + g;
                a[mi][0] = ldh2(&Xs[ ar   *SH + ks*16 + 2*t    ]);
                a[mi][1] = ldh2(&Xs[(ar+8)*SH + ks*16 + 2*t    ]);
                a[mi][2] = ldh2(&Xs[ ar   *SH + ks*16 + 2*t + 8]);
                a[mi][3] = ldh2(&Xs[(ar+8)*SH + ks*16 + 2*t + 8]);
            }
            #pragma unroll
            for (int nt = 0; nt < 4; nt++) {
                const __half* Bb = Ws + (wc*32 + nt*8 + g)*SH;
                uint32_t b0 = ldh2(Bb + ks*16 + 2*t);
                uint32_t b1 = ldh2(Bb + ks*16 + 2*t + 8);
                #pragma unroll
                for (int mi = 0; mi < 2; mi++)
                    MMA_F16(oacc[mi][nt][0], oacc[mi][nt][1], oacc[mi][nt][2], oacc[mi][nt][3],
                            a[mi][0], a[mi][1], a[mi][2], a[mi][3], b0, b1);
            }
        }
        __syncthreads();
        if (e < 15) {
            *(uint4*)&Xs[rrA*SH + ccA] = pX[0];
            *(uint4*)&Xs[rrB*SH + ccB] = pX[1];
            *(uint4*)&Ws[rrA*SH + ccA] = pW[0];
            *(uint4*)&Ws[rrB*SH + ccB] = pW[1];
        }
    }

    #pragma unroll
    for (int mi = 0; mi < 2; mi++) {
        size_t ra = r0 + wr*32 + mi*16 + g;
        #pragma unroll
        for (int nt = 0; nt < 4; nt++) {
            size_t c = n0 + wc*32 + nt*8 + 2*t;
            float bv0 = bfc[c], bv1 = bfc[c+1];
            *(float2*)(out + ra*EMBN + c) =
                make_float2(oacc[mi][nt][0] + bv0, oacc[mi][nt][1] + bv1);
            *(float2*)(out + (ra+8)*EMBN + c) =
                make_float2(oacc[mi][nt][2] + bv0, oacc[mi][nt][3] + bv1);
        }
    }
}

// ---------------------------------------------------------------------------
extern "C" void kernel_launch(void* const* d_in, const int* in_sizes, int n_in,
                              void* d_out, int out_size)
{
    const float* query = (const float*)d_in[0];
    const float* key_  = (const float*)d_in[1];
    const float* value = (const float*)d_in[2];
    const int*   mask  = (const int*)d_in[3];
    const float* Wq = (const float*)d_in[4];
    const float* bq = (const float*)d_in[5];
    const float* Wk = (const float*)d_in[6];
    const float* bk = (const float*)d_in[7];
    const float* Wv = (const float*)d_in[8];
    const float* bv = (const float*)d_in[9];
    const float* Wfc = (const float*)d_in[10];
    const float* bfc = (const float*)d_in[11];
    const float* relk = (const float*)d_in[12];
    const float* relv = (const float*)d_in[13];
    float* out = (float*)d_out;

    cudaFuncSetAttribute(attn_kernel, cudaFuncAttributeMaxDynamicSharedMemorySize, ATT_SMEM_BYTES);

    pre_kernel<<<dim3(1024, 4, 1), 256>>>(query, key_, value, Wq, bq, Wk, bk, Wv, bv,
                                          relk, relv, Wfc, mask);
    attn_kernel<<<dim3(LL/QB, HH, BB), 256, ATT_SMEM_BYTES>>>();
    fc_kernel<<<dim3(32, 8, 1), 512>>>(bfc, out);
}